// round 1
// baseline (speedup 1.0000x reference)
#include <cuda_runtime.h>
#include <math.h>

// ---------------- sizes ----------------
constexpr int B = 32;

// ---------------- scratch (device globals; no allocation allowed) ----------------
__device__ float g_h1[B * 32 * 128 * 128];   // encoder conv1 out
__device__ float g_h2[B * 64 * 64 * 64];     // encoder conv2 out
__device__ float g_z [B * 8 * 64 * 64];      // latent z (NCHW)
__device__ float g_zq[B * 8 * 64 * 64];      // quantized (buggy NCHW reinterpret)
__device__ int   g_idx[B * 64 * 64];         // 131072 indices (NHWC position order)
__device__ float g_part[4096];               // loss partials
__device__ float g_d1[B * 64 * 64 * 64];     // decoder conv1 out
__device__ float g_t1[B * 64 * 128 * 128];   // dect1 out
__device__ float g_t2[B * 32 * 256 * 256];   // dect2 out

constexpr int XR_ELEMS  = B * 3 * 256 * 256;  // 6291456
constexpr int LOSS_OFF  = XR_ELEMS;           // 6291456
constexpr int IDX_OFF   = XR_ELEMS + 1;       // 6291457

// =====================================================================
// Encoder conv1: 3->32, k4 s2 p1, 256x256 -> 128x128, ReLU
// grid: B*64 blocks x 256 threads (one thread per output pixel, 32 couts)
// =====================================================================
__global__ __launch_bounds__(256) void k_conv1(const float* __restrict__ x,
                                               const float* __restrict__ w,
                                               const float* __restrict__ bias) {
    __shared__ float ws[48 * 32];  // [ci*16 + ky*4 + kx][co]
    for (int i = threadIdx.x; i < 48 * 32; i += 256) {
        int t = i >> 5, co = i & 31;
        int ci = t >> 4, k = t & 15;
        ws[i] = w[(co * 3 + ci) * 16 + k];
    }
    __syncthreads();
    int n = blockIdx.x >> 6;
    int p = ((blockIdx.x & 63) << 8) + threadIdx.x;  // 0..16383
    int oy = p >> 7, ox = p & 127;
    float acc[32];
#pragma unroll
    for (int c = 0; c < 32; c++) acc[c] = bias[c];
    const float* xin = x + (size_t)n * 3 * 256 * 256;
    for (int ci = 0; ci < 3; ci++) {
#pragma unroll
        for (int ky = 0; ky < 4; ky++) {
            int iy = 2 * oy + ky - 1;
            if ((unsigned)iy >= 256u) continue;
#pragma unroll
            for (int kx = 0; kx < 4; kx++) {
                int ix = 2 * ox + kx - 1;
                if ((unsigned)ix >= 256u) continue;
                float v = xin[(ci * 256 + iy) * 256 + ix];
                const float* wr = &ws[(ci * 16 + ky * 4 + kx) * 32];
#pragma unroll
                for (int co = 0; co < 32; co++) acc[co] = fmaf(v, wr[co], acc[co]);
            }
        }
    }
    float* o = g_h1 + (size_t)n * 32 * 128 * 128;
#pragma unroll
    for (int co = 0; co < 32; co++)
        o[(co * 128 + oy) * 128 + ox] = fmaxf(acc[co], 0.f);
}

// =====================================================================
// Encoder conv2: 32->64, k4 s2 p1, 128x128 -> 64x64, ReLU
// weights staged in ci-chunks of 8 (32KB smem). grid: B*16 x 256
// =====================================================================
__global__ __launch_bounds__(256) void k_conv2(const float* __restrict__ w,
                                               const float* __restrict__ bias) {
    __shared__ float ws[8 * 16 * 64];  // [cl*16+k][co]
    int n = blockIdx.x >> 4;
    int p = ((blockIdx.x & 15) << 8) + threadIdx.x;  // 0..4095
    int oy = p >> 6, ox = p & 63;
    float acc[64];
#pragma unroll
    for (int c = 0; c < 64; c++) acc[c] = bias[c];
    const float* xin = g_h1 + (size_t)n * 32 * 128 * 128;
    for (int cc = 0; cc < 4; cc++) {
        __syncthreads();
        for (int i = threadIdx.x; i < 8 * 16 * 64; i += 256) {
            int t = i >> 6, co = i & 63;
            int cl = t >> 4, k = t & 15;
            ws[i] = w[(co * 32 + cc * 8 + cl) * 16 + k];
        }
        __syncthreads();
        for (int cl = 0; cl < 8; cl++) {
            int ci = cc * 8 + cl;
#pragma unroll
            for (int ky = 0; ky < 4; ky++) {
                int iy = 2 * oy + ky - 1;
                if ((unsigned)iy >= 128u) continue;
#pragma unroll
                for (int kx = 0; kx < 4; kx++) {
                    int ix = 2 * ox + kx - 1;
                    if ((unsigned)ix >= 128u) continue;
                    float v = xin[(ci * 128 + iy) * 128 + ix];
                    const float* wr = &ws[(cl * 16 + ky * 4 + kx) * 64];
#pragma unroll
                    for (int co = 0; co < 64; co++) acc[co] = fmaf(v, wr[co], acc[co]);
                }
            }
        }
    }
    float* o = g_h2 + (size_t)n * 64 * 64 * 64;
#pragma unroll
    for (int co = 0; co < 64; co++)
        o[co * 4096 + p] = fmaxf(acc[co], 0.f);
}

// =====================================================================
// Encoder conv3: 1x1, 64->8. grid: B*16 x 256
// =====================================================================
__global__ __launch_bounds__(256) void k_conv3(const float* __restrict__ w,
                                               const float* __restrict__ bias) {
    __shared__ float ws[64 * 8];  // [ci][co]
    for (int i = threadIdx.x; i < 512; i += 256) {
        int ci = i >> 3, co = i & 7;
        ws[i] = w[co * 64 + ci];
    }
    __syncthreads();
    int n = blockIdx.x >> 4;
    int p = ((blockIdx.x & 15) << 8) + threadIdx.x;
    float acc[8];
#pragma unroll
    for (int c = 0; c < 8; c++) acc[c] = bias[c];
    const float* xin = g_h2 + (size_t)n * 64 * 4096;
    for (int ci = 0; ci < 64; ci++) {
        float v = xin[ci * 4096 + p];
#pragma unroll
        for (int co = 0; co < 8; co++) acc[co] = fmaf(v, ws[ci * 8 + co], acc[co]);
    }
    float* o = g_z + (size_t)n * 8 * 4096;
#pragma unroll
    for (int co = 0; co < 8; co++) o[co * 4096 + p] = acc[co];
}

// =====================================================================
// VQ argmin: per NHWC position, distance to 512 codes (codebook in smem)
// grid: 1024 x 128
// =====================================================================
__global__ __launch_bounds__(128) void k_vq(const float* __restrict__ cb) {
    __shared__ float cs[512 * 8];
    __shared__ float csq[512];
    for (int i = threadIdx.x; i < 4096; i += 128) cs[i] = cb[i];
    __syncthreads();
    for (int k = threadIdx.x; k < 512; k += 128) {
        float s = 0.f;
#pragma unroll
        for (int d = 0; d < 8; d++) { float c = cs[k * 8 + d]; s += c * c; }
        csq[k] = s;
    }
    __syncthreads();
    int p = blockIdx.x * 128 + threadIdx.x;  // < 131072, = b*4096 + y*64 + x
    int n = p >> 12, hw = p & 4095;
    const float* zp = g_z + (size_t)n * 8 * 4096 + hw;
    float zv[8]; float zsq = 0.f;
#pragma unroll
    for (int d = 0; d < 8; d++) { zv[d] = zp[d * 4096]; zsq += zv[d] * zv[d]; }
    float best = 3.4e38f; int bi = 0;
    for (int k = 0; k < 512; k++) {
        float dot = 0.f;
#pragma unroll
        for (int d = 0; d < 8; d++) dot = fmaf(zv[d], cs[k * 8 + d], dot);
        float dist = zsq + csq[k] - 2.f * dot;
        if (dist < best) { best = dist; bi = k; }  // strict <: first-min like jnp.argmin
    }
    g_idx[p] = bi;
}

// =====================================================================
// z_q gather (faithful to reference layout bug) + per-block loss partials
// grid: 4096 x 256  (1048576 elements)
// =====================================================================
__global__ __launch_bounds__(256) void k_zq(const float* __restrict__ cb) {
    int i = blockIdx.x * 256 + threadIdx.x;   // NCHW linear index into z / z_q
    float q = cb[g_idx[i >> 3] * 8 + (i & 7)];
    g_zq[i] = q;
    float diff = g_z[i] - q;
    float v = diff * diff;
    __shared__ float red[256];
    red[threadIdx.x] = v; __syncthreads();
    for (int s = 128; s > 0; s >>= 1) {
        if (threadIdx.x < s) red[threadIdx.x] += red[threadIdx.x + s];
        __syncthreads();
    }
    if (threadIdx.x == 0) g_part[blockIdx.x] = red[0];
}

// Deterministic final loss reduction; vq_loss = (1 + 0.25) * MSE
__global__ __launch_bounds__(256) void k_loss(float* __restrict__ out) {
    __shared__ float red[256];
    float s = 0.f;
    for (int i = threadIdx.x; i < 4096; i += 256) s += g_part[i];
    red[threadIdx.x] = s; __syncthreads();
    for (int st = 128; st > 0; st >>= 1) {
        if (threadIdx.x < st) red[threadIdx.x] += red[threadIdx.x + st];
        __syncthreads();
    }
    if (threadIdx.x == 0) out[LOSS_OFF] = red[0] * (1.25f / 1048576.f);
}

__global__ __launch_bounds__(256) void k_idxout(float* __restrict__ out) {
    int p = blockIdx.x * 256 + threadIdx.x;
    if (p < B * 4096) out[IDX_OFF + p] = (float)g_idx[p];
}

// =====================================================================
// Decoder conv1: 3x3 p1, 8->64, 64x64, ReLU. grid: B*16 x 256
// =====================================================================
__global__ __launch_bounds__(256) void k_dconv1(const float* __restrict__ w,
                                                const float* __restrict__ bias) {
    __shared__ float ws[8 * 9 * 64];  // 18KB, [ci*9+k][co]
    for (int i = threadIdx.x; i < 8 * 9 * 64; i += 256) {
        int t = i >> 6, co = i & 63;
        int ci = t / 9, k = t % 9;
        ws[i] = w[(co * 8 + ci) * 9 + k];
    }
    __syncthreads();
    int n = blockIdx.x >> 4;
    int p = ((blockIdx.x & 15) << 8) + threadIdx.x;
    int oy = p >> 6, ox = p & 63;
    float acc[64];
#pragma unroll
    for (int c = 0; c < 64; c++) acc[c] = bias[c];
    const float* xin = g_zq + (size_t)n * 8 * 4096;
#pragma unroll
    for (int ci = 0; ci < 8; ci++) {
#pragma unroll
        for (int ky = 0; ky < 3; ky++) {
            int iy = oy + ky - 1;
            if ((unsigned)iy >= 64u) continue;
#pragma unroll
            for (int kx = 0; kx < 3; kx++) {
                int ix = ox + kx - 1;
                if ((unsigned)ix >= 64u) continue;
                float v = xin[(ci * 64 + iy) * 64 + ix];
                const float* wr = &ws[(ci * 9 + ky * 3 + kx) * 64];
#pragma unroll
                for (int co = 0; co < 64; co++) acc[co] = fmaf(v, wr[co], acc[co]);
            }
        }
    }
    float* o = g_d1 + (size_t)n * 64 * 4096;
#pragma unroll
    for (int co = 0; co < 64; co++) o[co * 4096 + p] = fmaxf(acc[co], 0.f);
}

// =====================================================================
// Transposed conv 1: 64->64, k4 s2 p1, 64x64 -> 128x128, ReLU
// exactly <=2x2 valid taps per output. ci-chunks of 8. grid: B*64 x 256
// =====================================================================
__global__ __launch_bounds__(256) void k_dect1(const float* __restrict__ w,
                                               const float* __restrict__ bias) {
    __shared__ float ws[8 * 16 * 64];  // 32KB
    int n = blockIdx.x >> 6;
    int p = ((blockIdx.x & 63) << 8) + threadIdx.x;  // 0..16383
    int oy = p >> 7, ox = p & 127;
    float acc[64];
#pragma unroll
    for (int c = 0; c < 64; c++) acc[c] = bias[c];
    const float* xin = g_d1 + (size_t)n * 64 * 4096;
    int pyo = oy & 1, pxo = ox & 1;
    for (int cc = 0; cc < 8; cc++) {
        __syncthreads();
        for (int i = threadIdx.x; i < 8 * 16 * 64; i += 256) {
            int t = i >> 6, co = i & 63;
            int cl = t >> 4, k = t & 15;
            ws[i] = w[(co * 64 + cc * 8 + cl) * 16 + k];
        }
        __syncthreads();
#pragma unroll
        for (int cl = 0; cl < 8; cl++) {
            int ci = cc * 8 + cl;
#pragma unroll
            for (int ty = 0; ty < 2; ty++) {
                int ky = pyo + 2 * ty;
                int iy = (oy + ky - 2) >> 1;
                if ((unsigned)iy >= 64u) continue;
#pragma unroll
                for (int tx = 0; tx < 2; tx++) {
                    int kx = pxo + 2 * tx;
                    int ix = (ox + kx - 2) >> 1;
                    if ((unsigned)ix >= 64u) continue;
                    float v = xin[(ci * 64 + iy) * 64 + ix];
                    const float* wr = &ws[(cl * 16 + ky * 4 + kx) * 64];
#pragma unroll
                    for (int co = 0; co < 64; co++) acc[co] = fmaf(v, wr[co], acc[co]);
                }
            }
        }
    }
    float* o = g_t1 + (size_t)n * 64 * 128 * 128;
#pragma unroll
    for (int co = 0; co < 64; co++)
        o[co * 16384 + p] = fmaxf(acc[co], 0.f);
}

// =====================================================================
// Transposed conv 2: 64->32, k4 s2 p1, 128x128 -> 256x256, ReLU
// ci-chunks of 16. grid: B*256 x 256
// =====================================================================
__global__ __launch_bounds__(256) void k_dect2(const float* __restrict__ w,
                                               const float* __restrict__ bias) {
    __shared__ float ws[16 * 16 * 32];  // 32KB
    int n = blockIdx.x >> 8;
    int p = ((blockIdx.x & 255) << 8) + threadIdx.x;  // 0..65535
    int oy = p >> 8, ox = p & 255;
    float acc[32];
#pragma unroll
    for (int c = 0; c < 32; c++) acc[c] = bias[c];
    const float* xin = g_t1 + (size_t)n * 64 * 16384;
    int pyo = oy & 1, pxo = ox & 1;
    for (int cc = 0; cc < 4; cc++) {
        __syncthreads();
        for (int i = threadIdx.x; i < 16 * 16 * 32; i += 256) {
            int t = i >> 5, co = i & 31;
            int cl = t >> 4, k = t & 15;
            ws[i] = w[(co * 64 + cc * 16 + cl) * 16 + k];
        }
        __syncthreads();
#pragma unroll
        for (int cl = 0; cl < 16; cl++) {
            int ci = cc * 16 + cl;
#pragma unroll
            for (int ty = 0; ty < 2; ty++) {
                int ky = pyo + 2 * ty;
                int iy = (oy + ky - 2) >> 1;
                if ((unsigned)iy >= 128u) continue;
#pragma unroll
                for (int tx = 0; tx < 2; tx++) {
                    int kx = pxo + 2 * tx;
                    int ix = (ox + kx - 2) >> 1;
                    if ((unsigned)ix >= 128u) continue;
                    float v = xin[(ci * 128 + iy) * 128 + ix];
                    const float* wr = &ws[(cl * 16 + ky * 4 + kx) * 32];
#pragma unroll
                    for (int co = 0; co < 32; co++) acc[co] = fmaf(v, wr[co], acc[co]);
                }
            }
        }
    }
    float* o = g_t2 + (size_t)n * 32 * 65536;
#pragma unroll
    for (int co = 0; co < 32; co++)
        o[co * 65536 + p] = fmaxf(acc[co], 0.f);
}

// =====================================================================
// Decoder conv2: 3x3 p1, 32->3, sigmoid -> x_recon (into d_out). grid: B*256 x 256
// =====================================================================
__global__ __launch_bounds__(256) void k_dconv2(const float* __restrict__ w,
                                                const float* __restrict__ bias,
                                                float* __restrict__ out) {
    __shared__ float ws[32 * 9 * 4];  // [ci*9+k][co], pad co to 4
    for (int i = threadIdx.x; i < 32 * 9; i += 256) {
        int ci = i / 9, k = i % 9;
        ws[i * 4 + 0] = w[(0 * 32 + ci) * 9 + k];
        ws[i * 4 + 1] = w[(1 * 32 + ci) * 9 + k];
        ws[i * 4 + 2] = w[(2 * 32 + ci) * 9 + k];
        ws[i * 4 + 3] = 0.f;
    }
    __syncthreads();
    int n = blockIdx.x >> 8;
    int p = ((blockIdx.x & 255) << 8) + threadIdx.x;
    int oy = p >> 8, ox = p & 255;
    float a0 = bias[0], a1 = bias[1], a2 = bias[2];
    const float* xin = g_t2 + (size_t)n * 32 * 65536;
    for (int ci = 0; ci < 32; ci++) {
#pragma unroll
        for (int ky = 0; ky < 3; ky++) {
            int iy = oy + ky - 1;
            if ((unsigned)iy >= 256u) continue;
#pragma unroll
            for (int kx = 0; kx < 3; kx++) {
                int ix = ox + kx - 1;
                if ((unsigned)ix >= 256u) continue;
                float v = xin[(ci * 256 + iy) * 256 + ix];
                const float* wr = &ws[(ci * 9 + ky * 3 + kx) * 4];
                a0 = fmaf(v, wr[0], a0);
                a1 = fmaf(v, wr[1], a1);
                a2 = fmaf(v, wr[2], a2);
            }
        }
    }
    float* o = out + (size_t)n * 3 * 65536;
    o[0 * 65536 + p] = 1.f / (1.f + expf(-a0));
    o[1 * 65536 + p] = 1.f / (1.f + expf(-a1));
    o[2 * 65536 + p] = 1.f / (1.f + expf(-a2));
}

// =====================================================================
extern "C" void kernel_launch(void* const* d_in, const int* in_sizes, int n_in,
                              void* d_out, int out_size) {
    const float* x       = (const float*)d_in[0];
    const float* enc_w1  = (const float*)d_in[1];
    const float* enc_b1  = (const float*)d_in[2];
    const float* enc_w2  = (const float*)d_in[3];
    const float* enc_b2  = (const float*)d_in[4];
    const float* enc_w3  = (const float*)d_in[5];
    const float* enc_b3  = (const float*)d_in[6];
    const float* codebook= (const float*)d_in[7];
    const float* dec_w1  = (const float*)d_in[8];
    const float* dec_b1  = (const float*)d_in[9];
    const float* dect_w1 = (const float*)d_in[10];
    const float* dect_b1 = (const float*)d_in[11];
    const float* dect_w2 = (const float*)d_in[12];
    const float* dect_b2 = (const float*)d_in[13];
    const float* dec_w2  = (const float*)d_in[14];
    const float* dec_b2  = (const float*)d_in[15];
    float* out = (float*)d_out;

    k_conv1 <<<B * 64,  256>>>(x, enc_w1, enc_b1);
    k_conv2 <<<B * 16,  256>>>(enc_w2, enc_b2);
    k_conv3 <<<B * 16,  256>>>(enc_w3, enc_b3);
    k_vq    <<<1024,    128>>>(codebook);
    k_zq    <<<4096,    256>>>(codebook);
    k_loss  <<<1,       256>>>(out);
    k_idxout<<<512,     256>>>(out);
    k_dconv1<<<B * 16,  256>>>(dec_w1, dec_b1);
    k_dect1 <<<B * 64,  256>>>(dect_w1, dect_b1);
    k_dect2 <<<B * 256, 256>>>(dect_w2, dect_b2);
    k_dconv2<<<B * 256, 256>>>(dec_w2, dec_b2, out);
}

// round 2
// speedup vs baseline: 1.6798x; 1.6798x over previous
#include <cuda_runtime.h>
#include <math.h>

// ---------------- sizes ----------------
constexpr int B = 32;

// ---------------- padded scratch (device globals; zero-init => halos stay 0) ----
// h1p: [B][32][130][130]  (conv1 out, halo 1 for k4s2p1 consumer)
// h2 : [B][64][64][64]    (dense; only 1x1 consumer)
// z  : [B][8][64][64]
// zqp: [B][8][66][66]     (halo 1 for 3x3 consumer)
// d1p: [B][64][66][66]    (halo 1 for dect1)
// t1p: [B][64][130][130]  (halo 1 for dect2)
// t2p: [B][32][258][258]  (halo 1 for 3x3 consumer)
__device__ float g_h1p[B * 32 * 130 * 130];
__device__ float g_h2 [B * 64 * 64 * 64];
__device__ float g_z  [B * 8 * 64 * 64];
__device__ float g_zqp[B * 8 * 66 * 66];
__device__ int   g_idx[B * 64 * 64];
__device__ float g_part[4096];
__device__ float g_d1p[B * 64 * 66 * 66];
__device__ float g_t1p[B * 64 * 130 * 130];
__device__ float g_t2p[B * 32 * 258 * 258];

constexpr int XR_ELEMS = B * 3 * 256 * 256;
constexpr int LOSS_OFF = XR_ELEMS;
constexpr int IDX_OFF  = XR_ELEMS + 1;

constexpr int P130 = 130 * 130;  // 16900
constexpr int P66  = 66 * 66;    // 4356
constexpr int P258 = 258 * 258;  // 66564

// =====================================================================
// Encoder conv1: 3->32, k4 s2 p1, 256->128, ReLU. writes h1p interior.
// grid: B*64 x 256
// =====================================================================
__global__ __launch_bounds__(256) void k_conv1(const float* __restrict__ x,
                                               const float* __restrict__ w,
                                               const float* __restrict__ bias) {
    __shared__ float ws[48 * 32];  // [ci*16+k][co]
    for (int i = threadIdx.x; i < 48 * 32; i += 256) {
        int t = i >> 5, co = i & 31;
        int ci = t >> 4, k = t & 15;
        ws[i] = w[(co * 3 + ci) * 16 + k];
    }
    __syncthreads();
    int n = blockIdx.x >> 6;
    int p = ((blockIdx.x & 63) << 8) + threadIdx.x;
    int oy = p >> 7, ox = p & 127;
    float acc[32];
#pragma unroll
    for (int c = 0; c < 32; c++) acc[c] = bias[c];
    const float* xin = x + (size_t)n * 3 * 65536;
#pragma unroll
    for (int ci = 0; ci < 3; ci++) {
#pragma unroll
        for (int ky = 0; ky < 4; ky++) {
            int iy = 2 * oy + ky - 1;
            if ((unsigned)iy >= 256u) continue;
#pragma unroll
            for (int kx = 0; kx < 4; kx++) {
                int ix = 2 * ox + kx - 1;
                if ((unsigned)ix >= 256u) continue;
                float v = xin[(ci * 256 + iy) * 256 + ix];
                const float* wr = &ws[(ci * 16 + ky * 4 + kx) * 32];
#pragma unroll
                for (int co = 0; co < 32; co++) acc[co] = fmaf(v, wr[co], acc[co]);
            }
        }
    }
    float* o = g_h1p + (size_t)n * 32 * P130 + (oy + 1) * 130 + ox + 1;
#pragma unroll
    for (int co = 0; co < 32; co++)
        o[co * P130] = fmaxf(acc[co], 0.f);
}

// =====================================================================
// Encoder conv2: 32->64, k4 s2 p1, 128->64, ReLU. branch-free via h1p halo.
// grid: B*16 x 256
// =====================================================================
__global__ __launch_bounds__(256) void k_conv2(const float* __restrict__ w,
                                               const float* __restrict__ bias) {
    __shared__ float ws[8 * 16 * 64];
    int n = blockIdx.x >> 4;
    int p = ((blockIdx.x & 15) << 8) + threadIdx.x;
    int oy = p >> 6, ox = p & 63;
    float acc[64];
#pragma unroll
    for (int c = 0; c < 64; c++) acc[c] = bias[c];
    const float* xin = g_h1p + (size_t)n * 32 * P130;
    for (int cc = 0; cc < 4; cc++) {
        __syncthreads();
        for (int i = threadIdx.x; i < 8 * 16 * 64; i += 256) {
            int t = i >> 6, co = i & 63;
            int cl = t >> 4, k = t & 15;
            ws[i] = w[(co * 32 + cc * 8 + cl) * 16 + k];
        }
        __syncthreads();
#pragma unroll
        for (int cl = 0; cl < 8; cl++) {
            const float* pl = xin + (cc * 8 + cl) * P130;
#pragma unroll
            for (int ky = 0; ky < 4; ky++) {
                const float* row = pl + (2 * oy + ky) * 130 + 2 * ox;  // 8B aligned
#pragma unroll
                for (int kp = 0; kp < 2; kp++) {
                    float2 v2 = *(const float2*)(row + 2 * kp);
                    const float* w0 = &ws[(cl * 16 + ky * 4 + 2 * kp) * 64];
                    const float* w1 = w0 + 64;
#pragma unroll
                    for (int co = 0; co < 64; co++) {
                        acc[co] = fmaf(v2.x, w0[co], acc[co]);
                        acc[co] = fmaf(v2.y, w1[co], acc[co]);
                    }
                }
            }
        }
    }
    float* o = g_h2 + (size_t)n * 64 * 4096;
#pragma unroll
    for (int co = 0; co < 64; co++)
        o[co * 4096 + p] = fmaxf(acc[co], 0.f);
}

// =====================================================================
// Encoder conv3: 1x1, 64->8. grid: B*16 x 256
// =====================================================================
__global__ __launch_bounds__(256) void k_conv3(const float* __restrict__ w,
                                               const float* __restrict__ bias) {
    __shared__ float ws[64 * 8];
    for (int i = threadIdx.x; i < 512; i += 256) {
        int ci = i >> 3, co = i & 7;
        ws[i] = w[co * 64 + ci];
    }
    __syncthreads();
    int n = blockIdx.x >> 4;
    int p = ((blockIdx.x & 15) << 8) + threadIdx.x;
    float acc[8];
#pragma unroll
    for (int c = 0; c < 8; c++) acc[c] = bias[c];
    const float* xin = g_h2 + (size_t)n * 64 * 4096;
#pragma unroll 8
    for (int ci = 0; ci < 64; ci++) {
        float v = xin[ci * 4096 + p];
#pragma unroll
        for (int co = 0; co < 8; co++) acc[co] = fmaf(v, ws[ci * 8 + co], acc[co]);
    }
    float* o = g_z + (size_t)n * 8 * 4096;
#pragma unroll
    for (int co = 0; co < 8; co++) o[co * 4096 + p] = acc[co];
}

// =====================================================================
// VQ argmin per NHWC position. grid: 1024 x 128
// =====================================================================
__global__ __launch_bounds__(128) void k_vq(const float* __restrict__ cb) {
    __shared__ float cs[512 * 8];
    __shared__ float csq[512];
    for (int i = threadIdx.x; i < 4096; i += 128) cs[i] = cb[i];
    __syncthreads();
    for (int k = threadIdx.x; k < 512; k += 128) {
        float s = 0.f;
#pragma unroll
        for (int d = 0; d < 8; d++) { float c = cs[k * 8 + d]; s += c * c; }
        csq[k] = s;
    }
    __syncthreads();
    int p = blockIdx.x * 128 + threadIdx.x;
    int n = p >> 12, hw = p & 4095;
    const float* zp = g_z + (size_t)n * 8 * 4096 + hw;
    float zv[8]; float zsq = 0.f;
#pragma unroll
    for (int d = 0; d < 8; d++) { zv[d] = zp[d * 4096]; zsq += zv[d] * zv[d]; }
    float best = 3.4e38f; int bi = 0;
    for (int k = 0; k < 512; k++) {
        float dot = 0.f;
#pragma unroll
        for (int d = 0; d < 8; d++) dot = fmaf(zv[d], cs[k * 8 + d], dot);
        float dist = zsq + csq[k] - 2.f * dot;
        if (dist < best) { best = dist; bi = k; }
    }
    g_idx[p] = bi;
}

// =====================================================================
// z_q gather (faithful layout bug) -> zqp padded; per-block loss partials.
// grid: 4096 x 256
// =====================================================================
__global__ __launch_bounds__(256) void k_zq(const float* __restrict__ cb) {
    int i = blockIdx.x * 256 + threadIdx.x;  // NCHW linear
    float q = cb[g_idx[i >> 3] * 8 + (i & 7)];
    int n = i >> 15, c = (i >> 12) & 7, hw = i & 4095;
    int y = hw >> 6, xx = hw & 63;
    g_zqp[(size_t)(n * 8 + c) * P66 + (y + 1) * 66 + xx + 1] = q;
    float diff = g_z[i] - q;
    float v = diff * diff;
    __shared__ float red[256];
    red[threadIdx.x] = v; __syncthreads();
    for (int s = 128; s > 0; s >>= 1) {
        if (threadIdx.x < s) red[threadIdx.x] += red[threadIdx.x + s];
        __syncthreads();
    }
    if (threadIdx.x == 0) g_part[blockIdx.x] = red[0];
}

__global__ __launch_bounds__(256) void k_loss(float* __restrict__ out) {
    __shared__ float red[256];
    float s = 0.f;
    for (int i = threadIdx.x; i < 4096; i += 256) s += g_part[i];
    red[threadIdx.x] = s; __syncthreads();
    for (int st = 128; st > 0; st >>= 1) {
        if (threadIdx.x < st) red[threadIdx.x] += red[threadIdx.x + st];
        __syncthreads();
    }
    if (threadIdx.x == 0) out[LOSS_OFF] = red[0] * (1.25f / 1048576.f);
}

__global__ __launch_bounds__(256) void k_idxout(float* __restrict__ out) {
    int p = blockIdx.x * 256 + threadIdx.x;
    if (p < B * 4096) out[IDX_OFF + p] = (float)g_idx[p];
}

// =====================================================================
// Decoder conv1: 3x3 p1, 8->64, 64x64, ReLU. branch-free via zqp halo.
// grid: B*16 x 256
// =====================================================================
__global__ __launch_bounds__(256) void k_dconv1(const float* __restrict__ w,
                                                const float* __restrict__ bias) {
    __shared__ float ws[8 * 9 * 64];
    for (int i = threadIdx.x; i < 8 * 9 * 64; i += 256) {
        int t = i >> 6, co = i & 63;
        int ci = t / 9, k = t % 9;
        ws[i] = w[(co * 8 + ci) * 9 + k];
    }
    __syncthreads();
    int n = blockIdx.x >> 4;
    int p = ((blockIdx.x & 15) << 8) + threadIdx.x;
    int oy = p >> 6, ox = p & 63;
    float acc[64];
#pragma unroll
    for (int c = 0; c < 64; c++) acc[c] = bias[c];
    const float* xin = g_zqp + (size_t)n * 8 * P66;
#pragma unroll
    for (int ci = 0; ci < 8; ci++) {
        const float* pl = xin + ci * P66;
#pragma unroll
        for (int ky = 0; ky < 3; ky++) {
            const float* row = pl + (oy + ky) * 66 + ox;
#pragma unroll
            for (int kx = 0; kx < 3; kx++) {
                float v = row[kx];
                const float* wr = &ws[(ci * 9 + ky * 3 + kx) * 64];
#pragma unroll
                for (int co = 0; co < 64; co++) acc[co] = fmaf(v, wr[co], acc[co]);
            }
        }
    }
    float* o = g_d1p + (size_t)n * 64 * P66 + (oy + 1) * 66 + ox + 1;
#pragma unroll
    for (int co = 0; co < 64; co++) o[co * P66] = fmaxf(acc[co], 0.f);
}

// =====================================================================
// Transposed conv 1: 64->64, k4 s2 p1, 64->128, ReLU. branch-free.
// 512 threads: 2 co-groups x 256 pixel-threads; 2 same-parity rows/thread.
// grid: B*32 x 512
// =====================================================================
__global__ __launch_bounds__(512) void k_dect1(const float* __restrict__ w,
                                               const float* __restrict__ bias) {
    __shared__ float ws[8 * 16 * 64];  // [cl*16+k][co], 32KB
    int n = blockIdx.x >> 5;
    int g = threadIdx.x >> 8;            // co-group: 0 or 1 (co = g*32 + c)
    int q = threadIdx.x & 255;
    int p = ((blockIdx.x & 31) << 8) + q;  // 0..8191
    int ox = p & 127, t = p >> 7;          // t in 0..63
    int r = t >> 1, py = t & 1;
    int R = 2 * r + py;                    // input row center, 0..63
    int X = ox >> 1, px = ox & 1;

    float acc0[32], acc1[32];
#pragma unroll
    for (int c = 0; c < 32; c++) { acc0[c] = bias[g * 32 + c]; acc1[c] = acc0[c]; }

    const float* xin = g_d1p + (size_t)n * 64 * P66;
    int colbase = X + px;  // = ix0+1
    for (int cc = 0; cc < 8; cc++) {
        __syncthreads();
        for (int i = threadIdx.x; i < 8 * 16 * 64; i += 512) {
            int tt = i >> 6, co = i & 63;
            int cl = tt >> 4, k = tt & 15;
            ws[i] = w[(co * 64 + cc * 8 + cl) * 16 + k];
        }
        __syncthreads();
#pragma unroll
        for (int cl = 0; cl < 8; cl++) {
            const float* pl = xin + (cc * 8 + cl) * P66;
            const float* rowa = pl + R * 66 + colbase;        // iy = R-1
            const float* rowb = rowa + 66;                    // iy = R
            const float* rowc = rowb + 66;                    // iy = R+1
            float a0 = rowa[0], a1 = rowa[1];
            float b0 = rowb[0], b1 = rowb[1];
            float c0 = rowc[0], c1 = rowc[1];
            const float* w00 = &ws[(cl * 16 + py * 4 + px) * 64] + g * 32;
            const float* w01 = w00 + 2 * 64;        // kx = px+2
            const float* w10 = w00 + 2 * 4 * 64;    // ky = py+2
            const float* w11 = w10 + 2 * 64;
#pragma unroll
            for (int c = 0; c < 32; c++) {
                acc0[c] = fmaf(a0, w00[c], acc0[c]);
                acc0[c] = fmaf(a1, w01[c], acc0[c]);
                acc0[c] = fmaf(b0, w10[c], acc0[c]);
                acc0[c] = fmaf(b1, w11[c], acc0[c]);
                acc1[c] = fmaf(b0, w00[c], acc1[c]);
                acc1[c] = fmaf(b1, w01[c], acc1[c]);
                acc1[c] = fmaf(c0, w10[c], acc1[c]);
                acc1[c] = fmaf(c1, w11[c], acc1[c]);
            }
        }
    }
    int oy0 = 4 * r + py;
    float* o = g_t1p + (size_t)n * 64 * P130 + (size_t)g * 32 * P130
             + (oy0 + 1) * 130 + ox + 1;
#pragma unroll
    for (int c = 0; c < 32; c++) {
        o[c * P130]            = fmaxf(acc0[c], 0.f);
        o[c * P130 + 2 * 130]  = fmaxf(acc1[c], 0.f);
    }
}

// =====================================================================
// Transposed conv 2: 64->32, k4 s2 p1, 128->256, ReLU. branch-free.
// 2 same-parity rows per thread. grid: B*128 x 256
// =====================================================================
__global__ __launch_bounds__(256) void k_dect2(const float* __restrict__ w,
                                               const float* __restrict__ bias) {
    __shared__ float ws[16 * 16 * 32];  // 32KB
    int n = blockIdx.x >> 7;
    int p = ((blockIdx.x & 127) << 8) + threadIdx.x;  // 0..32767
    int ox = p & 255, t = p >> 8;                     // t 0..127
    int r = t >> 1, py = t & 1;
    int R = 2 * r + py;                               // 0..127
    int X = ox >> 1, px = ox & 1;

    float acc0[32], acc1[32];
#pragma unroll
    for (int c = 0; c < 32; c++) { acc0[c] = bias[c]; acc1[c] = acc0[c]; }

    const float* xin = g_t1p + (size_t)n * 64 * P130;
    int colbase = X + px;
    for (int cc = 0; cc < 4; cc++) {
        __syncthreads();
        for (int i = threadIdx.x; i < 16 * 16 * 32; i += 256) {
            int tt = i >> 5, co = i & 31;
            int cl = tt >> 4, k = tt & 15;
            ws[i] = w[(co * 64 + cc * 16 + cl) * 16 + k];
        }
        __syncthreads();
#pragma unroll
        for (int cl = 0; cl < 16; cl++) {
            const float* pl = xin + (cc * 16 + cl) * P130;
            const float* rowa = pl + R * 130 + colbase;
            const float* rowb = rowa + 130;
            const float* rowc = rowb + 130;
            float a0 = rowa[0], a1 = rowa[1];
            float b0 = rowb[0], b1 = rowb[1];
            float c0 = rowc[0], c1 = rowc[1];
            const float* w00 = &ws[(cl * 16 + py * 4 + px) * 32];
            const float* w01 = w00 + 2 * 32;
            const float* w10 = w00 + 2 * 4 * 32;
            const float* w11 = w10 + 2 * 32;
#pragma unroll
            for (int c = 0; c < 32; c++) {
                acc0[c] = fmaf(a0, w00[c], acc0[c]);
                acc0[c] = fmaf(a1, w01[c], acc0[c]);
                acc0[c] = fmaf(b0, w10[c], acc0[c]);
                acc0[c] = fmaf(b1, w11[c], acc0[c]);
                acc1[c] = fmaf(b0, w00[c], acc1[c]);
                acc1[c] = fmaf(b1, w01[c], acc1[c]);
                acc1[c] = fmaf(c0, w10[c], acc1[c]);
                acc1[c] = fmaf(c1, w11[c], acc1[c]);
            }
        }
    }
    int oy0 = 4 * r + py;
    float* o = g_t2p + (size_t)n * 32 * P258 + (oy0 + 1) * 258 + ox + 1;
#pragma unroll
    for (int c = 0; c < 32; c++) {
        o[c * P258]           = fmaxf(acc0[c], 0.f);
        o[c * P258 + 2 * 258] = fmaxf(acc1[c], 0.f);
    }
}

// =====================================================================
// Decoder conv2: 3x3 p1, 32->3, sigmoid. 4 pixels/thread, branch-free.
// grid: B*64 x 256
// =====================================================================
__global__ __launch_bounds__(256) void k_dconv2(const float* __restrict__ w,
                                                const float* __restrict__ bias,
                                                float* __restrict__ out) {
    __shared__ float ws[32 * 9 * 4];  // [ci*9+k][co(3)+pad]
    for (int i = threadIdx.x; i < 32 * 9; i += 256) {
        int ci = i / 9, k = i % 9;
        ws[i * 4 + 0] = w[(0 * 32 + ci) * 9 + k];
        ws[i * 4 + 1] = w[(1 * 32 + ci) * 9 + k];
        ws[i * 4 + 2] = w[(2 * 32 + ci) * 9 + k];
        ws[i * 4 + 3] = 0.f;
    }
    __syncthreads();
    int n = blockIdx.x >> 6;
    int p = ((blockIdx.x & 63) << 8) + threadIdx.x;  // 0..16383
    int X = p & 63, oy = p >> 6;                     // ox0 = 4X, oy 0..255
    int ox0 = 4 * X;

    float acc[3][4];
#pragma unroll
    for (int co = 0; co < 3; co++) {
        float bv = bias[co];
#pragma unroll
        for (int j = 0; j < 4; j++) acc[co][j] = bv;
    }
    const float* xin = g_t2p + (size_t)n * 32 * P258;
#pragma unroll 4
    for (int ci = 0; ci < 32; ci++) {
        const float* pl = xin + ci * P258;
        float in[3][6];
#pragma unroll
        for (int ry = 0; ry < 3; ry++) {
            const float* row = pl + (oy + ry) * 258 + ox0;  // 8B aligned
            float2 v0 = *(const float2*)(row);
            float2 v1 = *(const float2*)(row + 2);
            float2 v2 = *(const float2*)(row + 4);
            in[ry][0] = v0.x; in[ry][1] = v0.y;
            in[ry][2] = v1.x; in[ry][3] = v1.y;
            in[ry][4] = v2.x; in[ry][5] = v2.y;
        }
#pragma unroll
        for (int ky = 0; ky < 3; ky++) {
#pragma unroll
            for (int kx = 0; kx < 3; kx++) {
                const float* wr = &ws[(ci * 9 + ky * 3 + kx) * 4];
                float w0 = wr[0], w1 = wr[1], w2 = wr[2];
#pragma unroll
                for (int j = 0; j < 4; j++) {
                    float v = in[ky][j + kx];
                    acc[0][j] = fmaf(v, w0, acc[0][j]);
                    acc[1][j] = fmaf(v, w1, acc[1][j]);
                    acc[2][j] = fmaf(v, w2, acc[2][j]);
                }
            }
        }
    }
    float* o = out + (size_t)n * 3 * 65536 + oy * 256 + ox0;
#pragma unroll
    for (int co = 0; co < 3; co++)
#pragma unroll
        for (int j = 0; j < 4; j++)
            o[co * 65536 + j] = 1.f / (1.f + expf(-acc[co][j]));
}

// =====================================================================
extern "C" void kernel_launch(void* const* d_in, const int* in_sizes, int n_in,
                              void* d_out, int out_size) {
    const float* x       = (const float*)d_in[0];
    const float* enc_w1  = (const float*)d_in[1];
    const float* enc_b1  = (const float*)d_in[2];
    const float* enc_w2  = (const float*)d_in[3];
    const float* enc_b2  = (const float*)d_in[4];
    const float* enc_w3  = (const float*)d_in[5];
    const float* enc_b3  = (const float*)d_in[6];
    const float* codebook= (const float*)d_in[7];
    const float* dec_w1  = (const float*)d_in[8];
    const float* dec_b1  = (const float*)d_in[9];
    const float* dect_w1 = (const float*)d_in[10];
    const float* dect_b1 = (const float*)d_in[11];
    const float* dect_w2 = (const float*)d_in[12];
    const float* dect_b2 = (const float*)d_in[13];
    const float* dec_w2  = (const float*)d_in[14];
    const float* dec_b2  = (const float*)d_in[15];
    float* out = (float*)d_out;

    k_conv1 <<<B * 64,  256>>>(x, enc_w1, enc_b1);
    k_conv2 <<<B * 16,  256>>>(enc_w2, enc_b2);
    k_conv3 <<<B * 16,  256>>>(enc_w3, enc_b3);
    k_vq    <<<1024,    128>>>(codebook);
    k_zq    <<<4096,    256>>>(codebook);
    k_loss  <<<1,       256>>>(out);
    k_idxout<<<512,     256>>>(out);
    k_dconv1<<<B * 16,  256>>>(dec_w1, dec_b1);
    k_dect1 <<<B * 32,  512>>>(dect_w1, dect_b1);
    k_dect2 <<<B * 128, 256>>>(dect_w2, dect_b2);
    k_dconv2<<<B * 64,  256>>>(dec_w2, dec_b2, out);
}

// round 3
// speedup vs baseline: 1.6926x; 1.0076x over previous
#include <cuda_runtime.h>
#include <math.h>

// ---------------- sizes ----------------
constexpr int B = 32;

// ---------------- packed f32x2 helpers (Blackwell sm_103a) ----------------
typedef unsigned long long u64;
#define FFMA2(acc, v, w) \
    asm("fma.rn.f32x2 %0, %1, %2, %3;" : "=l"(acc) : "l"(v), "l"(w), "l"(acc))
__device__ __forceinline__ u64 pack2(float a, float b) {
    u64 r; asm("mov.b64 %0, {%1, %2};" : "=l"(r) : "f"(a), "f"(b)); return r;
}
__device__ __forceinline__ float2 unpack2(u64 v) {
    float2 f; asm("mov.b64 {%0, %1}, %2;" : "=f"(f.x), "=f"(f.y) : "l"(v)); return f;
}

// ---------------- padded scratch (zero-init => halos stay 0) ----------------
__device__ float g_h1p[B * 32 * 130 * 130];
__device__ float g_h2 [B * 64 * 64 * 64];
__device__ float g_z  [B * 8 * 64 * 64];
__device__ float g_zqp[B * 8 * 66 * 66];
__device__ int   g_idx[B * 64 * 64];
__device__ float g_part[4096];
__device__ float g_d1p[B * 64 * 66 * 66];
__device__ float g_t1p[B * 64 * 130 * 130];
__device__ float g_t2p[B * 32 * 258 * 258];

constexpr int XR_ELEMS = B * 3 * 256 * 256;
constexpr int LOSS_OFF = XR_ELEMS;
constexpr int IDX_OFF  = XR_ELEMS + 1;

constexpr int P130 = 130 * 130;
constexpr int P66  = 66 * 66;
constexpr int P258 = 258 * 258;

// =====================================================================
// Encoder conv1: 3->32, k4 s2 p1, 256->128, ReLU. grid: B*64 x 256
// =====================================================================
__global__ __launch_bounds__(256) void k_conv1(const float* __restrict__ x,
                                               const float* __restrict__ w,
                                               const float* __restrict__ bias) {
    __shared__ float ws[48 * 32];  // [ci*16+k][co]
    for (int i = threadIdx.x; i < 48 * 32; i += 256) {
        int t = i >> 5, co = i & 31;
        int ci = t >> 4, k = t & 15;
        ws[i] = w[(co * 3 + ci) * 16 + k];
    }
    __syncthreads();
    int n = blockIdx.x >> 6;
    int p = ((blockIdx.x & 63) << 8) + threadIdx.x;
    int oy = p >> 7, ox = p & 127;
    u64 acc[16];
#pragma unroll
    for (int c = 0; c < 16; c++) acc[c] = pack2(bias[2 * c], bias[2 * c + 1]);
    const float* xin = x + (size_t)n * 3 * 65536;
#pragma unroll
    for (int ci = 0; ci < 3; ci++) {
#pragma unroll
        for (int ky = 0; ky < 4; ky++) {
            int iy = 2 * oy + ky - 1;
            if ((unsigned)iy >= 256u) continue;
#pragma unroll
            for (int kx = 0; kx < 4; kx++) {
                int ix = 2 * ox + kx - 1;
                if ((unsigned)ix >= 256u) continue;
                float v = xin[(ci * 256 + iy) * 256 + ix];
                u64 vv = pack2(v, v);
                const u64* wr = (const u64*)&ws[(ci * 16 + ky * 4 + kx) * 32];
#pragma unroll
                for (int c = 0; c < 16; c++) FFMA2(acc[c], vv, wr[c]);
            }
        }
    }
    float* o = g_h1p + (size_t)n * 32 * P130 + (oy + 1) * 130 + ox + 1;
#pragma unroll
    for (int c = 0; c < 16; c++) {
        float2 f = unpack2(acc[c]);
        o[(2 * c)     * P130] = fmaxf(f.x, 0.f);
        o[(2 * c + 1) * P130] = fmaxf(f.y, 0.f);
    }
}

// =====================================================================
// Encoder conv2: 32->64, k4 s2 p1, 128->64, ReLU. grid: B*16 x 256
// =====================================================================
__global__ __launch_bounds__(256) void k_conv2(const float* __restrict__ w,
                                               const float* __restrict__ bias) {
    __shared__ float ws[8 * 16 * 64];
    int n = blockIdx.x >> 4;
    int p = ((blockIdx.x & 15) << 8) + threadIdx.x;
    int oy = p >> 6, ox = p & 63;
    u64 acc[32];
#pragma unroll
    for (int c = 0; c < 32; c++) acc[c] = pack2(bias[2 * c], bias[2 * c + 1]);
    const float* xin = g_h1p + (size_t)n * 32 * P130;
    for (int cc = 0; cc < 4; cc++) {
        __syncthreads();
        for (int i = threadIdx.x; i < 8 * 16 * 64; i += 256) {
            int t = i >> 6, co = i & 63;
            int cl = t >> 4, k = t & 15;
            ws[i] = w[(co * 32 + cc * 8 + cl) * 16 + k];
        }
        __syncthreads();
#pragma unroll
        for (int cl = 0; cl < 8; cl++) {
            const float* pl = xin + (cc * 8 + cl) * P130;
#pragma unroll
            for (int ky = 0; ky < 4; ky++) {
                const float* row = pl + (2 * oy + ky) * 130 + 2 * ox;
#pragma unroll
                for (int kp = 0; kp < 2; kp++) {
                    float2 v2 = *(const float2*)(row + 2 * kp);
                    u64 vx = pack2(v2.x, v2.x), vy = pack2(v2.y, v2.y);
                    const u64* w0 = (const u64*)&ws[(cl * 16 + ky * 4 + 2 * kp) * 64];
                    const u64* w1 = w0 + 32;
#pragma unroll
                    for (int c = 0; c < 32; c++) {
                        FFMA2(acc[c], vx, w0[c]);
                        FFMA2(acc[c], vy, w1[c]);
                    }
                }
            }
        }
    }
    float* o = g_h2 + (size_t)n * 64 * 4096;
#pragma unroll
    for (int c = 0; c < 32; c++) {
        float2 f = unpack2(acc[c]);
        o[(2 * c)     * 4096 + p] = fmaxf(f.x, 0.f);
        o[(2 * c + 1) * 4096 + p] = fmaxf(f.y, 0.f);
    }
}

// =====================================================================
// Encoder conv3: 1x1, 64->8. grid: B*16 x 256
// =====================================================================
__global__ __launch_bounds__(256) void k_conv3(const float* __restrict__ w,
                                               const float* __restrict__ bias) {
    __shared__ float ws[64 * 8];
    for (int i = threadIdx.x; i < 512; i += 256) {
        int ci = i >> 3, co = i & 7;
        ws[i] = w[co * 64 + ci];
    }
    __syncthreads();
    int n = blockIdx.x >> 4;
    int p = ((blockIdx.x & 15) << 8) + threadIdx.x;
    u64 acc[4];
#pragma unroll
    for (int c = 0; c < 4; c++) acc[c] = pack2(bias[2 * c], bias[2 * c + 1]);
    const float* xin = g_h2 + (size_t)n * 64 * 4096;
#pragma unroll 8
    for (int ci = 0; ci < 64; ci++) {
        float v = xin[ci * 4096 + p];
        u64 vv = pack2(v, v);
        const u64* wr = (const u64*)&ws[ci * 8];
#pragma unroll
        for (int c = 0; c < 4; c++) FFMA2(acc[c], vv, wr[c]);
    }
    float* o = g_z + (size_t)n * 8 * 4096;
#pragma unroll
    for (int c = 0; c < 4; c++) {
        float2 f = unpack2(acc[c]);
        o[(2 * c)     * 4096 + p] = f.x;
        o[(2 * c + 1) * 4096 + p] = f.y;
    }
}

// =====================================================================
// VQ argmin per NHWC position. grid: 1024 x 128
// =====================================================================
__global__ __launch_bounds__(128) void k_vq(const float* __restrict__ cb) {
    __shared__ float cs[512 * 8];
    __shared__ float csq[512];
    for (int i = threadIdx.x; i < 4096; i += 128) cs[i] = cb[i];
    __syncthreads();
    for (int k = threadIdx.x; k < 512; k += 128) {
        float s = 0.f;
#pragma unroll
        for (int d = 0; d < 8; d++) { float c = cs[k * 8 + d]; s += c * c; }
        csq[k] = s;
    }
    __syncthreads();
    int p = blockIdx.x * 128 + threadIdx.x;
    int n = p >> 12, hw = p & 4095;
    const float* zp = g_z + (size_t)n * 8 * 4096 + hw;
    float zv[8]; float zsq = 0.f;
#pragma unroll
    for (int d = 0; d < 8; d++) { zv[d] = zp[d * 4096]; zsq += zv[d] * zv[d]; }
    float best = 3.4e38f; int bi = 0;
    for (int k = 0; k < 512; k++) {
        float dot = 0.f;
#pragma unroll
        for (int d = 0; d < 8; d++) dot = fmaf(zv[d], cs[k * 8 + d], dot);
        float dist = zsq + csq[k] - 2.f * dot;
        if (dist < best) { best = dist; bi = k; }
    }
    g_idx[p] = bi;
}

// =====================================================================
// z_q gather (faithful layout bug) + loss partials. grid: 4096 x 256
// =====================================================================
__global__ __launch_bounds__(256) void k_zq(const float* __restrict__ cb) {
    int i = blockIdx.x * 256 + threadIdx.x;
    float q = cb[g_idx[i >> 3] * 8 + (i & 7)];
    int n = i >> 15, c = (i >> 12) & 7, hw = i & 4095;
    int y = hw >> 6, xx = hw & 63;
    g_zqp[(size_t)(n * 8 + c) * P66 + (y + 1) * 66 + xx + 1] = q;
    float diff = g_z[i] - q;
    float v = diff * diff;
    __shared__ float red[256];
    red[threadIdx.x] = v; __syncthreads();
    for (int s = 128; s > 0; s >>= 1) {
        if (threadIdx.x < s) red[threadIdx.x] += red[threadIdx.x + s];
        __syncthreads();
    }
    if (threadIdx.x == 0) g_part[blockIdx.x] = red[0];
}

__global__ __launch_bounds__(256) void k_loss(float* __restrict__ out) {
    __shared__ float red[256];
    float s = 0.f;
    for (int i = threadIdx.x; i < 4096; i += 256) s += g_part[i];
    red[threadIdx.x] = s; __syncthreads();
    for (int st = 128; st > 0; st >>= 1) {
        if (threadIdx.x < st) red[threadIdx.x] += red[threadIdx.x + st];
        __syncthreads();
    }
    if (threadIdx.x == 0) out[LOSS_OFF] = red[0] * (1.25f / 1048576.f);
}

__global__ __launch_bounds__(256) void k_idxout(float* __restrict__ out) {
    int p = blockIdx.x * 256 + threadIdx.x;
    if (p < B * 4096) out[IDX_OFF + p] = (float)g_idx[p];
}

// =====================================================================
// Decoder conv1: 3x3 p1, 8->64, ReLU. grid: B*16 x 256
// =====================================================================
__global__ __launch_bounds__(256) void k_dconv1(const float* __restrict__ w,
                                                const float* __restrict__ bias) {
    __shared__ float ws[8 * 9 * 64];
    for (int i = threadIdx.x; i < 8 * 9 * 64; i += 256) {
        int t = i >> 6, co = i & 63;
        int ci = t / 9, k = t % 9;
        ws[i] = w[(co * 8 + ci) * 9 + k];
    }
    __syncthreads();
    int n = blockIdx.x >> 4;
    int p = ((blockIdx.x & 15) << 8) + threadIdx.x;
    int oy = p >> 6, ox = p & 63;
    u64 acc[32];
#pragma unroll
    for (int c = 0; c < 32; c++) acc[c] = pack2(bias[2 * c], bias[2 * c + 1]);
    const float* xin = g_zqp + (size_t)n * 8 * P66;
#pragma unroll
    for (int ci = 0; ci < 8; ci++) {
        const float* pl = xin + ci * P66;
#pragma unroll
        for (int ky = 0; ky < 3; ky++) {
            const float* row = pl + (oy + ky) * 66 + ox;
#pragma unroll
            for (int kx = 0; kx < 3; kx++) {
                float v = row[kx];
                u64 vv = pack2(v, v);
                const u64* wr = (const u64*)&ws[(ci * 9 + ky * 3 + kx) * 64];
#pragma unroll
                for (int c = 0; c < 32; c++) FFMA2(acc[c], vv, wr[c]);
            }
        }
    }
    float* o = g_d1p + (size_t)n * 64 * P66 + (oy + 1) * 66 + ox + 1;
#pragma unroll
    for (int c = 0; c < 32; c++) {
        float2 f = unpack2(acc[c]);
        o[(2 * c)     * P66] = fmaxf(f.x, 0.f);
        o[(2 * c + 1) * P66] = fmaxf(f.y, 0.f);
    }
}

// =====================================================================
// Transposed conv 1: 64->64, k4 s2 p1, 64->128, ReLU. grid: B*32 x 512
// 2 co-groups x 256 pixel-threads; 2 same-parity rows/thread.
// =====================================================================
__global__ __launch_bounds__(512) void k_dect1(const float* __restrict__ w,
                                               const float* __restrict__ bias) {
    __shared__ float ws[8 * 16 * 64];
    int n = blockIdx.x >> 5;
    int g = threadIdx.x >> 8;
    int q = threadIdx.x & 255;
    int p = ((blockIdx.x & 31) << 8) + q;
    int ox = p & 127, t = p >> 7;
    int r = t >> 1, py = t & 1;
    int R = 2 * r + py;
    int X = ox >> 1, px = ox & 1;

    u64 acc0[16], acc1[16];
#pragma unroll
    for (int c = 0; c < 16; c++) {
        acc0[c] = pack2(bias[g * 32 + 2 * c], bias[g * 32 + 2 * c + 1]);
        acc1[c] = acc0[c];
    }
    const float* xin = g_d1p + (size_t)n * 64 * P66;
    int colbase = X + px;
    for (int cc = 0; cc < 8; cc++) {
        __syncthreads();
        for (int i = threadIdx.x; i < 8 * 16 * 64; i += 512) {
            int tt = i >> 6, co = i & 63;
            int cl = tt >> 4, k = tt & 15;
            ws[i] = w[(co * 64 + cc * 8 + cl) * 16 + k];
        }
        __syncthreads();
#pragma unroll
        for (int cl = 0; cl < 8; cl++) {
            const float* pl = xin + (cc * 8 + cl) * P66;
            const float* rowa = pl + R * 66 + colbase;
            const float* rowb = rowa + 66;
            const float* rowc = rowb + 66;
            u64 a0 = pack2(rowa[0], rowa[0]), a1 = pack2(rowa[1], rowa[1]);
            u64 b0 = pack2(rowb[0], rowb[0]), b1 = pack2(rowb[1], rowb[1]);
            u64 c0 = pack2(rowc[0], rowc[0]), c1 = pack2(rowc[1], rowc[1]);
            const u64* w00 = (const u64*)(&ws[(cl * 16 + py * 4 + px) * 64] + g * 32);
            const u64* w01 = w00 + 64;           // kx = px+2 (2*64 floats = 64 u64)
            const u64* w10 = w00 + 256;          // ky = py+2 (2*4*64 floats)
            const u64* w11 = w10 + 64;
#pragma unroll
            for (int c = 0; c < 16; c++) {
                FFMA2(acc0[c], a0, w00[c]);
                FFMA2(acc0[c], a1, w01[c]);
                FFMA2(acc0[c], b0, w10[c]);
                FFMA2(acc0[c], b1, w11[c]);
                FFMA2(acc1[c], b0, w00[c]);
                FFMA2(acc1[c], b1, w01[c]);
                FFMA2(acc1[c], c0, w10[c]);
                FFMA2(acc1[c], c1, w11[c]);
            }
        }
    }
    int oy0 = 4 * r + py;
    float* o = g_t1p + (size_t)n * 64 * P130 + (size_t)g * 32 * P130
             + (oy0 + 1) * 130 + ox + 1;
#pragma unroll
    for (int c = 0; c < 16; c++) {
        float2 f0 = unpack2(acc0[c]);
        float2 f1 = unpack2(acc1[c]);
        o[(2 * c)     * P130]            = fmaxf(f0.x, 0.f);
        o[(2 * c + 1) * P130]            = fmaxf(f0.y, 0.f);
        o[(2 * c)     * P130 + 2 * 130]  = fmaxf(f1.x, 0.f);
        o[(2 * c + 1) * P130 + 2 * 130]  = fmaxf(f1.y, 0.f);
    }
}

// =====================================================================
// Transposed conv 2: 64->32, k4 s2 p1, 128->256, ReLU. grid: B*128 x 256
// =====================================================================
__global__ __launch_bounds__(256) void k_dect2(const float* __restrict__ w,
                                               const float* __restrict__ bias) {
    __shared__ float ws[16 * 16 * 32];
    int n = blockIdx.x >> 7;
    int p = ((blockIdx.x & 127) << 8) + threadIdx.x;
    int ox = p & 255, t = p >> 8;
    int r = t >> 1, py = t & 1;
    int R = 2 * r + py;
    int X = ox >> 1, px = ox & 1;

    u64 acc0[16], acc1[16];
#pragma unroll
    for (int c = 0; c < 16; c++) {
        acc0[c] = pack2(bias[2 * c], bias[2 * c + 1]);
        acc1[c] = acc0[c];
    }
    const float* xin = g_t1p + (size_t)n * 64 * P130;
    int colbase = X + px;
    for (int cc = 0; cc < 4; cc++) {
        __syncthreads();
        for (int i = threadIdx.x; i < 16 * 16 * 32; i += 256) {
            int tt = i >> 5, co = i & 31;
            int cl = tt >> 4, k = tt & 15;
            ws[i] = w[(co * 64 + cc * 16 + cl) * 16 + k];
        }
        __syncthreads();
#pragma unroll
        for (int cl = 0; cl < 16; cl++) {
            const float* pl = xin + (cc * 16 + cl) * P130;
            const float* rowa = pl + R * 130 + colbase;
            const float* rowb = rowa + 130;
            const float* rowc = rowb + 130;
            u64 a0 = pack2(rowa[0], rowa[0]), a1 = pack2(rowa[1], rowa[1]);
            u64 b0 = pack2(rowb[0], rowb[0]), b1 = pack2(rowb[1], rowb[1]);
            u64 c0 = pack2(rowc[0], rowc[0]), c1 = pack2(rowc[1], rowc[1]);
            const u64* w00 = (const u64*)&ws[(cl * 16 + py * 4 + px) * 32];
            const u64* w01 = w00 + 32;     // kx = px+2 (2*32 floats)
            const u64* w10 = w00 + 128;    // ky = py+2 (2*4*32 floats)
            const u64* w11 = w10 + 32;
#pragma unroll
            for (int c = 0; c < 16; c++) {
                FFMA2(acc0[c], a0, w00[c]);
                FFMA2(acc0[c], a1, w01[c]);
                FFMA2(acc0[c], b0, w10[c]);
                FFMA2(acc0[c], b1, w11[c]);
                FFMA2(acc1[c], b0, w00[c]);
                FFMA2(acc1[c], b1, w01[c]);
                FFMA2(acc1[c], c0, w10[c]);
                FFMA2(acc1[c], c1, w11[c]);
            }
        }
    }
    int oy0 = 4 * r + py;
    float* o = g_t2p + (size_t)n * 32 * P258 + (oy0 + 1) * 258 + ox + 1;
#pragma unroll
    for (int c = 0; c < 16; c++) {
        float2 f0 = unpack2(acc0[c]);
        float2 f1 = unpack2(acc1[c]);
        o[(2 * c)     * P258]           = fmaxf(f0.x, 0.f);
        o[(2 * c + 1) * P258]           = fmaxf(f0.y, 0.f);
        o[(2 * c)     * P258 + 2 * 258] = fmaxf(f1.x, 0.f);
        o[(2 * c + 1) * P258 + 2 * 258] = fmaxf(f1.y, 0.f);
    }
}

// =====================================================================
// Decoder conv2: 3x3 p1, 32->3, sigmoid. 4 px/thread, j-pairs packed.
// grid: B*64 x 256
// =====================================================================
__global__ __launch_bounds__(256) void k_dconv2(const float* __restrict__ w,
                                                const float* __restrict__ bias,
                                                float* __restrict__ out) {
    __shared__ u64 ws2[32 * 9 * 3];  // broadcast pairs (w,w), [ci*9+k][co]
    for (int i = threadIdx.x; i < 32 * 9; i += 256) {
        int ci = i / 9, k = i % 9;
#pragma unroll
        for (int co = 0; co < 3; co++) {
            float wv = w[(co * 32 + ci) * 9 + k];
            ws2[i * 3 + co] = pack2(wv, wv);
        }
    }
    __syncthreads();
    int n = blockIdx.x >> 6;
    int p = ((blockIdx.x & 63) << 8) + threadIdx.x;
    int X = p & 63, oy = p >> 6;
    int ox0 = 4 * X;

    u64 acc[3][2];  // [co][j-pair]: (j0,j1),(j2,j3)
#pragma unroll
    for (int co = 0; co < 3; co++) {
        float bv = bias[co];
        acc[co][0] = pack2(bv, bv);
        acc[co][1] = acc[co][0];
    }
    const float* xin = g_t2p + (size_t)n * 32 * P258;
#pragma unroll 2
    for (int ci = 0; ci < 32; ci++) {
        const float* pl = xin + ci * P258;
        float in[3][6];
#pragma unroll
        for (int ry = 0; ry < 3; ry++) {
            const float* row = pl + (oy + ry) * 258 + ox0;
            float2 v0 = *(const float2*)(row);
            float2 v1 = *(const float2*)(row + 2);
            float2 v2 = *(const float2*)(row + 4);
            in[ry][0] = v0.x; in[ry][1] = v0.y;
            in[ry][2] = v1.x; in[ry][3] = v1.y;
            in[ry][4] = v2.x; in[ry][5] = v2.y;
        }
        u64 pr[3][5];
#pragma unroll
        for (int ry = 0; ry < 3; ry++)
#pragma unroll
            for (int i = 0; i < 5; i++)
                pr[ry][i] = pack2(in[ry][i], in[ry][i + 1]);
#pragma unroll
        for (int ky = 0; ky < 3; ky++) {
#pragma unroll
            for (int kx = 0; kx < 3; kx++) {
                const u64* wr = &ws2[(ci * 9 + ky * 3 + kx) * 3];
#pragma unroll
                for (int co = 0; co < 3; co++) {
                    FFMA2(acc[co][0], pr[ky][kx],     wr[co]);
                    FFMA2(acc[co][1], pr[ky][kx + 2], wr[co]);
                }
            }
        }
    }
    float* o = out + (size_t)n * 3 * 65536 + oy * 256 + ox0;
#pragma unroll
    for (int co = 0; co < 3; co++) {
        float2 f0 = unpack2(acc[co][0]);
        float2 f1 = unpack2(acc[co][1]);
        o[co * 65536 + 0] = 1.f / (1.f + expf(-f0.x));
        o[co * 65536 + 1] = 1.f / (1.f + expf(-f0.y));
        o[co * 65536 + 2] = 1.f / (1.f + expf(-f1.x));
        o[co * 65536 + 3] = 1.f / (1.f + expf(-f1.y));
    }
}

// =====================================================================
extern "C" void kernel_launch(void* const* d_in, const int* in_sizes, int n_in,
                              void* d_out, int out_size) {
    const float* x       = (const float*)d_in[0];
    const float* enc_w1  = (const float*)d_in[1];
    const float* enc_b1  = (const float*)d_in[2];
    const float* enc_w2  = (const float*)d_in[3];
    const float* enc_b2  = (const float*)d_in[4];
    const float* enc_w3  = (const float*)d_in[5];
    const float* enc_b3  = (const float*)d_in[6];
    const float* codebook= (const float*)d_in[7];
    const float* dec_w1  = (const float*)d_in[8];
    const float* dec_b1  = (const float*)d_in[9];
    const float* dect_w1 = (const float*)d_in[10];
    const float* dect_b1 = (const float*)d_in[11];
    const float* dect_w2 = (const float*)d_in[12];
    const float* dect_b2 = (const float*)d_in[13];
    const float* dec_w2  = (const float*)d_in[14];
    const float* dec_b2  = (const float*)d_in[15];
    float* out = (float*)d_out;

    k_conv1 <<<B * 64,  256>>>(x, enc_w1, enc_b1);
    k_conv2 <<<B * 16,  256>>>(enc_w2, enc_b2);
    k_conv3 <<<B * 16,  256>>>(enc_w3, enc_b3);
    k_vq    <<<1024,    128>>>(codebook);
    k_zq    <<<4096,    256>>>(codebook);
    k_loss  <<<1,       256>>>(out);
    k_idxout<<<512,     256>>>(out);
    k_dconv1<<<B * 16,  256>>>(dec_w1, dec_b1);
    k_dect1 <<<B * 32,  512>>>(dect_w1, dect_b1);
    k_dect2 <<<B * 128, 256>>>(dect_w2, dect_b2);
    k_dconv2<<<B * 64,  256>>>(dec_w2, dec_b2, out);
}

// round 4
// speedup vs baseline: 1.9539x; 1.1544x over previous
#include <cuda_runtime.h>
#include <math.h>

constexpr int B = 32;

typedef unsigned long long u64;
#define FFMA2(acc, v, w) \
    asm("fma.rn.f32x2 %0, %1, %2, %3;" : "=l"(acc) : "l"(v), "l"(w), "l"(acc))
__device__ __forceinline__ u64 pack2(float a, float b) {
    u64 r; asm("mov.b64 %0, {%1, %2};" : "=l"(r) : "f"(a), "f"(b)); return r;
}
__device__ __forceinline__ float2 unpack2(u64 v) {
    float2 f; asm("mov.b64 {%0, %1}, %2;" : "=f"(f.x), "=f"(f.y) : "l"(v)); return f;
}

// ---- padded planes (strides multiple of 4 floats; halos stay zero forever) ----
constexpr int XP_P = 258 * 260;   // padded input x / t2p plane
constexpr int H1_P = 130 * 132;   // h1p & t1p plane
constexpr int Z_P  = 66 * 68;     // zqp & d1p plane

__device__ float g_xp [B * 3 * XP_P];
__device__ float g_h1p[B * 32 * H1_P];
__device__ float g_h2 [B * 64 * 4096];
__device__ float g_z  [B * 8 * 4096];
__device__ float g_zqp[B * 8 * Z_P];
__device__ int   g_idx[B * 4096];
__device__ float g_part[4096];
__device__ float g_d1p[B * 64 * Z_P];
__device__ float g_t1p[B * 64 * H1_P];
__device__ float g_t2p[B * 32 * XP_P];

constexpr int XR_ELEMS = B * 3 * 65536;
constexpr int LOSS_OFF = XR_ELEMS;
constexpr int IDX_OFF  = XR_ELEMS + 1;

// =====================================================================
// pad x into g_xp interior. grid: 24576 x 256
// =====================================================================
__global__ __launch_bounds__(256) void k_pad(const float* __restrict__ x) {
    int i = blockIdx.x * 256 + threadIdx.x;
    int c = i >> 16, hw = i & 65535;
    int y = hw >> 8, xx = hw & 255;
    g_xp[(size_t)c * XP_P + (y + 1) * 260 + xx + 1] = x[i];
}

// =====================================================================
// conv1: 3->32, k4 s2 p1, 256->128, ReLU. thread: 8co x 8px. grid 1024 x 256
// =====================================================================
__global__ __launch_bounds__(256) void k_conv1(const float* __restrict__ w,
                                               const float* __restrict__ bias) {
    __shared__ float ws[48 * 32];  // [(ci*16+k)*32 + co]
    for (int i = threadIdx.x; i < 1536; i += 256) {
        int t = i >> 5, co = i & 31;
        int ci = t >> 4, k = t & 15;
        ws[i] = w[(co * 3 + ci) * 16 + k];
    }
    __syncthreads();
    int n = blockIdx.x >> 5, oyg = blockIdx.x & 31;
    int cog = threadIdx.x >> 6, oyl = (threadIdx.x >> 4) & 3, v0 = threadIdx.x & 15;
    int oy = oyg * 4 + oyl, ox0 = v0 * 8;
    u64 acc[4][8];
#pragma unroll
    for (int cp = 0; cp < 4; cp++) {
        u64 bv = pack2(bias[cog * 8 + 2 * cp], bias[cog * 8 + 2 * cp + 1]);
#pragma unroll
        for (int j = 0; j < 8; j++) acc[cp][j] = bv;
    }
    const float* xin = g_xp + (size_t)n * 3 * XP_P;
#pragma unroll
    for (int ci = 0; ci < 3; ci++) {
        const float* pl = xin + ci * XP_P;
#pragma unroll
        for (int ky = 0; ky < 4; ky++) {
            const float* row = pl + (2 * oy + ky) * 260 + 2 * ox0;
            float f[18];
            *(float4*)&f[0]  = *(const float4*)(row);
            *(float4*)&f[4]  = *(const float4*)(row + 4);
            *(float4*)&f[8]  = *(const float4*)(row + 8);
            *(float4*)&f[12] = *(const float4*)(row + 12);
            *(float2*)&f[16] = *(const float2*)(row + 16);
            u64 fb[18];
#pragma unroll
            for (int i = 0; i < 18; i++) fb[i] = pack2(f[i], f[i]);
#pragma unroll
            for (int kx = 0; kx < 4; kx++) {
                const u64* wr = (const u64*)&ws[(ci * 16 + ky * 4 + kx) * 32 + cog * 8];
                u64 w0 = wr[0], w1 = wr[1], w2 = wr[2], w3 = wr[3];
#pragma unroll
                for (int j = 0; j < 8; j++) {
                    u64 vv = fb[2 * j + kx];
                    FFMA2(acc[0][j], vv, w0); FFMA2(acc[1][j], vv, w1);
                    FFMA2(acc[2][j], vv, w2); FFMA2(acc[3][j], vv, w3);
                }
            }
        }
    }
    float* o = g_h1p + (size_t)n * 32 * H1_P + (oy + 1) * 132 + ox0 + 1;
#pragma unroll
    for (int cp = 0; cp < 4; cp++)
#pragma unroll
        for (int j = 0; j < 8; j++) {
            float2 fo = unpack2(acc[cp][j]);
            o[(cog * 8 + 2 * cp)     * H1_P + j] = fmaxf(fo.x, 0.f);
            o[(cog * 8 + 2 * cp + 1) * H1_P + j] = fmaxf(fo.y, 0.f);
        }
}

// =====================================================================
// conv2: 32->64, k4 s2 p1, 128->64, ReLU. thread: 8co x 8px. grid 512 x 256
// =====================================================================
__global__ __launch_bounds__(256) void k_conv2(const float* __restrict__ w,
                                               const float* __restrict__ bias) {
    __shared__ float ws[8 * 16 * 64];  // 32KB
    int n = blockIdx.x >> 4, oyg = blockIdx.x & 15;
    int cog = threadIdx.x >> 5, oyl = (threadIdx.x >> 3) & 3, v0 = threadIdx.x & 7;
    int oy = oyg * 4 + oyl, ox0 = v0 * 8;
    u64 acc[4][8];
#pragma unroll
    for (int cp = 0; cp < 4; cp++) {
        u64 bv = pack2(bias[cog * 8 + 2 * cp], bias[cog * 8 + 2 * cp + 1]);
#pragma unroll
        for (int j = 0; j < 8; j++) acc[cp][j] = bv;
    }
    const float* xin = g_h1p + (size_t)n * 32 * H1_P;
    for (int cc = 0; cc < 4; cc++) {
        __syncthreads();
        for (int i = threadIdx.x; i < 8192; i += 256) {
            int t = i >> 6, co = i & 63;
            int cl = t >> 4, k = t & 15;
            ws[i] = w[(co * 32 + cc * 8 + cl) * 16 + k];
        }
        __syncthreads();
#pragma unroll
        for (int cl = 0; cl < 8; cl++) {
            const float* pl = xin + (cc * 8 + cl) * H1_P;
#pragma unroll
            for (int ky = 0; ky < 4; ky++) {
                const float* row = pl + (2 * oy + ky) * 132 + 2 * ox0;
                float f[18];
                *(float4*)&f[0]  = *(const float4*)(row);
                *(float4*)&f[4]  = *(const float4*)(row + 4);
                *(float4*)&f[8]  = *(const float4*)(row + 8);
                *(float4*)&f[12] = *(const float4*)(row + 12);
                *(float2*)&f[16] = *(const float2*)(row + 16);
                u64 fb[18];
#pragma unroll
                for (int i = 0; i < 18; i++) fb[i] = pack2(f[i], f[i]);
#pragma unroll
                for (int kx = 0; kx < 4; kx++) {
                    const u64* wr = (const u64*)&ws[(cl * 16 + ky * 4 + kx) * 64 + cog * 8];
                    u64 w0 = wr[0], w1 = wr[1], w2 = wr[2], w3 = wr[3];
#pragma unroll
                    for (int j = 0; j < 8; j++) {
                        u64 vv = fb[2 * j + kx];
                        FFMA2(acc[0][j], vv, w0); FFMA2(acc[1][j], vv, w1);
                        FFMA2(acc[2][j], vv, w2); FFMA2(acc[3][j], vv, w3);
                    }
                }
            }
        }
    }
    float* o = g_h2 + (size_t)n * 64 * 4096 + oy * 64 + ox0;
#pragma unroll
    for (int cp = 0; cp < 4; cp++)
#pragma unroll
        for (int j = 0; j < 8; j++) {
            float2 fo = unpack2(acc[cp][j]);
            o[(cog * 8 + 2 * cp)     * 4096 + j] = fmaxf(fo.x, 0.f);
            o[(cog * 8 + 2 * cp + 1) * 4096 + j] = fmaxf(fo.y, 0.f);
        }
}

// =====================================================================
// conv3: 1x1, 64->8. grid: 512 x 256
// =====================================================================
__global__ __launch_bounds__(256) void k_conv3(const float* __restrict__ w,
                                               const float* __restrict__ bias) {
    __shared__ float ws[64 * 8];
    for (int i = threadIdx.x; i < 512; i += 256) {
        int ci = i >> 3, co = i & 7;
        ws[i] = w[co * 64 + ci];
    }
    __syncthreads();
    int n = blockIdx.x >> 4;
    int p = ((blockIdx.x & 15) << 8) + threadIdx.x;
    u64 acc[4];
#pragma unroll
    for (int c = 0; c < 4; c++) acc[c] = pack2(bias[2 * c], bias[2 * c + 1]);
    const float* xin = g_h2 + (size_t)n * 64 * 4096;
#pragma unroll 8
    for (int ci = 0; ci < 64; ci++) {
        float v = xin[ci * 4096 + p];
        u64 vv = pack2(v, v);
        const u64* wr = (const u64*)&ws[ci * 8];
#pragma unroll
        for (int c = 0; c < 4; c++) FFMA2(acc[c], vv, wr[c]);
    }
    float* o = g_z + (size_t)n * 8 * 4096;
#pragma unroll
    for (int c = 0; c < 4; c++) {
        float2 f = unpack2(acc[c]);
        o[(2 * c)     * 4096 + p] = f.x;
        o[(2 * c + 1) * 4096 + p] = f.y;
    }
}

// =====================================================================
// VQ argmin. grid: 1024 x 128
// =====================================================================
__global__ __launch_bounds__(128) void k_vq(const float* __restrict__ cb) {
    __shared__ float cs[512 * 8];
    __shared__ float csq[512];
    for (int i = threadIdx.x; i < 4096; i += 128) cs[i] = cb[i];
    __syncthreads();
    for (int k = threadIdx.x; k < 512; k += 128) {
        float s = 0.f;
#pragma unroll
        for (int d = 0; d < 8; d++) { float c = cs[k * 8 + d]; s += c * c; }
        csq[k] = s;
    }
    __syncthreads();
    int p = blockIdx.x * 128 + threadIdx.x;
    int n = p >> 12, hw = p & 4095;
    const float* zp = g_z + (size_t)n * 8 * 4096 + hw;
    float zv[8]; float zsq = 0.f;
#pragma unroll
    for (int d = 0; d < 8; d++) { zv[d] = zp[d * 4096]; zsq += zv[d] * zv[d]; }
    float best = 3.4e38f; int bi = 0;
    for (int k = 0; k < 512; k++) {
        float dot = 0.f;
#pragma unroll
        for (int d = 0; d < 8; d++) dot = fmaf(zv[d], cs[k * 8 + d], dot);
        float dist = zsq + csq[k] - 2.f * dot;
        if (dist < best) { best = dist; bi = k; }
    }
    g_idx[p] = bi;
}

// =====================================================================
// z_q gather (faithful layout bug) + loss partials. grid: 4096 x 256
// =====================================================================
__global__ __launch_bounds__(256) void k_zq(const float* __restrict__ cb) {
    int i = blockIdx.x * 256 + threadIdx.x;
    float q = cb[g_idx[i >> 3] * 8 + (i & 7)];
    int n = i >> 15, c = (i >> 12) & 7, hw = i & 4095;
    int y = hw >> 6, xx = hw & 63;
    g_zqp[(size_t)(n * 8 + c) * Z_P + (y + 1) * 68 + xx + 1] = q;
    float diff = g_z[i] - q;
    float v = diff * diff;
    __shared__ float red[256];
    red[threadIdx.x] = v; __syncthreads();
    for (int s = 128; s > 0; s >>= 1) {
        if (threadIdx.x < s) red[threadIdx.x] += red[threadIdx.x + s];
        __syncthreads();
    }
    if (threadIdx.x == 0) g_part[blockIdx.x] = red[0];
}

__global__ __launch_bounds__(256) void k_loss(float* __restrict__ out) {
    __shared__ float red[256];
    float s = 0.f;
    for (int i = threadIdx.x; i < 4096; i += 256) s += g_part[i];
    red[threadIdx.x] = s; __syncthreads();
    for (int st = 128; st > 0; st >>= 1) {
        if (threadIdx.x < st) red[threadIdx.x] += red[threadIdx.x + st];
        __syncthreads();
    }
    if (threadIdx.x == 0) out[LOSS_OFF] = red[0] * (1.25f / 1048576.f);
}

__global__ __launch_bounds__(256) void k_idxout(float* __restrict__ out) {
    int p = blockIdx.x * 256 + threadIdx.x;
    if (p < B * 4096) out[IDX_OFF + p] = (float)g_idx[p];
}

// =====================================================================
// dconv1: 3x3 p1, 8->64, ReLU. thread: 8co x 8px. grid 512 x 256
// =====================================================================
__global__ __launch_bounds__(256) void k_dconv1(const float* __restrict__ w,
                                                const float* __restrict__ bias) {
    __shared__ float ws[8 * 9 * 64];  // [(ci*9+k)*64 + co]
    for (int i = threadIdx.x; i < 4608; i += 256) {
        int t = i >> 6, co = i & 63;
        int ci = t / 9, k = t % 9;
        ws[i] = w[(co * 8 + ci) * 9 + k];
    }
    __syncthreads();
    int n = blockIdx.x >> 4, oyg = blockIdx.x & 15;
    int cog = threadIdx.x >> 5, oyl = (threadIdx.x >> 3) & 3, v0 = threadIdx.x & 7;
    int oy = oyg * 4 + oyl, ox0 = v0 * 8;
    u64 acc[4][8];
#pragma unroll
    for (int cp = 0; cp < 4; cp++) {
        u64 bv = pack2(bias[cog * 8 + 2 * cp], bias[cog * 8 + 2 * cp + 1]);
#pragma unroll
        for (int j = 0; j < 8; j++) acc[cp][j] = bv;
    }
    const float* xin = g_zqp + (size_t)n * 8 * Z_P;
#pragma unroll
    for (int ci = 0; ci < 8; ci++) {
        const float* pl = xin + ci * Z_P;
#pragma unroll
        for (int ky = 0; ky < 3; ky++) {
            const float* row = pl + (oy + ky) * 68 + ox0;
            float f[10];
            *(float4*)&f[0] = *(const float4*)(row);
            *(float4*)&f[4] = *(const float4*)(row + 4);
            *(float2*)&f[8] = *(const float2*)(row + 8);
            u64 fb[10];
#pragma unroll
            for (int i = 0; i < 10; i++) fb[i] = pack2(f[i], f[i]);
#pragma unroll
            for (int kx = 0; kx < 3; kx++) {
                const u64* wr = (const u64*)&ws[(ci * 9 + ky * 3 + kx) * 64 + cog * 8];
                u64 w0 = wr[0], w1 = wr[1], w2 = wr[2], w3 = wr[3];
#pragma unroll
                for (int j = 0; j < 8; j++) {
                    u64 vv = fb[j + kx];
                    FFMA2(acc[0][j], vv, w0); FFMA2(acc[1][j], vv, w1);
                    FFMA2(acc[2][j], vv, w2); FFMA2(acc[3][j], vv, w3);
                }
            }
        }
    }
    float* o = g_d1p + (size_t)n * 64 * Z_P + (oy + 1) * 68 + ox0 + 1;
#pragma unroll
    for (int cp = 0; cp < 4; cp++)
#pragma unroll
        for (int j = 0; j < 8; j++) {
            float2 fo = unpack2(acc[cp][j]);
            o[(cog * 8 + 2 * cp)     * Z_P + j] = fmaxf(fo.x, 0.f);
            o[(cog * 8 + 2 * cp + 1) * Z_P + j] = fmaxf(fo.y, 0.f);
        }
}

// =====================================================================
// dect1: 64->64, k4 s2 p1, 64->128, ReLU. parity sub-conv, compile-time (PY,PX).
// out[2u+PY, 2v+PX] = sum_ci sum_{dy,dx} inP[ci][u+PY+dy][v+PX+dx] * W[..]
// thread: 8co x 8v. grid (512, 4) x 256
// =====================================================================
template<int PY, int PX>
__device__ __forceinline__ void dect1_body(const float* __restrict__ w,
                                           const float* __restrict__ bias) {
    __shared__ float ws[16 * 4 * 64];  // [(cl*4+dy*2+dx)*64 + co], 16KB
    int n = blockIdx.x >> 4, ug = blockIdx.x & 15;
    int cog = threadIdx.x >> 5, ul = (threadIdx.x >> 3) & 3, v0 = threadIdx.x & 7;
    int u = ug * 4 + ul;
    u64 acc[4][8];
#pragma unroll
    for (int cp = 0; cp < 4; cp++) {
        u64 bv = pack2(bias[cog * 8 + 2 * cp], bias[cog * 8 + 2 * cp + 1]);
#pragma unroll
        for (int j = 0; j < 8; j++) acc[cp][j] = bv;
    }
    const float* xin = g_d1p + (size_t)n * 64 * Z_P;
    for (int cc = 0; cc < 4; cc++) {
        __syncthreads();
        for (int i = threadIdx.x; i < 4096; i += 256) {
            int co = i & 63, t = i >> 6;
            int cl = t >> 2, tp = t & 3;
            ws[i] = w[(co * 64 + cc * 16 + cl) * 16
                      + (PY + 2 * (tp >> 1)) * 4 + PX + 2 * (tp & 1)];
        }
        __syncthreads();
#pragma unroll
        for (int cl = 0; cl < 16; cl++) {
            const float* pl = xin + (cc * 16 + cl) * Z_P;
            const float* r0 = pl + (u + PY) * 68 + v0 * 8;
            float f0[10], f1[10];
            *(float4*)&f0[0] = *(const float4*)(r0);
            *(float4*)&f0[4] = *(const float4*)(r0 + 4);
            *(float2*)&f0[8] = *(const float2*)(r0 + 8);
            *(float4*)&f1[0] = *(const float4*)(r0 + 68);
            *(float4*)&f1[4] = *(const float4*)(r0 + 72);
            *(float2*)&f1[8] = *(const float2*)(r0 + 76);
            u64 P0[9], P1[9];
#pragma unroll
            for (int i = 0; i < 9; i++) {
                P0[i] = pack2(f0[i + PX], f0[i + PX]);
                P1[i] = pack2(f1[i + PX], f1[i + PX]);
            }
            const u64* wb = (const u64*)&ws[cl * 4 * 64 + cog * 8];
            u64 w00[4], w01[4], w10[4], w11[4];
#pragma unroll
            for (int cp = 0; cp < 4; cp++) {
                w00[cp] = wb[cp]; w01[cp] = wb[32 + cp];
                w10[cp] = wb[64 + cp]; w11[cp] = wb[96 + cp];
            }
#pragma unroll
            for (int j = 0; j < 8; j++) {
#pragma unroll
                for (int cp = 0; cp < 4; cp++) {
                    FFMA2(acc[cp][j], P0[j],     w00[cp]);
                    FFMA2(acc[cp][j], P0[j + 1], w01[cp]);
                    FFMA2(acc[cp][j], P1[j],     w10[cp]);
                    FFMA2(acc[cp][j], P1[j + 1], w11[cp]);
                }
            }
        }
    }
    float* o = g_t1p + (size_t)n * 64 * H1_P + (2 * u + PY + 1) * 132
             + 2 * (v0 * 8) + PX + 1;
#pragma unroll
    for (int cp = 0; cp < 4; cp++)
#pragma unroll
        for (int j = 0; j < 8; j++) {
            float2 fo = unpack2(acc[cp][j]);
            o[(cog * 8 + 2 * cp)     * H1_P + 2 * j] = fmaxf(fo.x, 0.f);
            o[(cog * 8 + 2 * cp + 1) * H1_P + 2 * j] = fmaxf(fo.y, 0.f);
        }
}

__global__ __launch_bounds__(256) void k_dect1(const float* __restrict__ w,
                                               const float* __restrict__ bias) {
    switch (blockIdx.y) {
        case 0: dect1_body<0, 0>(w, bias); break;
        case 1: dect1_body<0, 1>(w, bias); break;
        case 2: dect1_body<1, 0>(w, bias); break;
        default: dect1_body<1, 1>(w, bias); break;
    }
}

// =====================================================================
// dect2: 64->32, k4 s2 p1, 128->256, ReLU. thread: 8co x 8v. grid (1024,4) x 256
// =====================================================================
template<int PY, int PX>
__device__ __forceinline__ void dect2_body(const float* __restrict__ w,
                                           const float* __restrict__ bias) {
    __shared__ float ws[32 * 4 * 32];  // [(cl*4+dy*2+dx)*32 + co], 16KB
    int n = blockIdx.x >> 5, ug = blockIdx.x & 31;
    int cog = threadIdx.x >> 6, ul = (threadIdx.x >> 4) & 3, v0 = threadIdx.x & 15;
    int u = ug * 4 + ul;
    u64 acc[4][8];
#pragma unroll
    for (int cp = 0; cp < 4; cp++) {
        u64 bv = pack2(bias[cog * 8 + 2 * cp], bias[cog * 8 + 2 * cp + 1]);
#pragma unroll
        for (int j = 0; j < 8; j++) acc[cp][j] = bv;
    }
    const float* xin = g_t1p + (size_t)n * 64 * H1_P;
    for (int cc = 0; cc < 2; cc++) {
        __syncthreads();
        for (int i = threadIdx.x; i < 4096; i += 256) {
            int co = i & 31, t = i >> 5;
            int cl = t >> 2, tp = t & 3;
            ws[i] = w[(co * 64 + cc * 32 + cl) * 16
                      + (PY + 2 * (tp >> 1)) * 4 + PX + 2 * (tp & 1)];
        }
        __syncthreads();
#pragma unroll
        for (int cl = 0; cl < 32; cl++) {
            const float* pl = xin + (cc * 32 + cl) * H1_P;
            const float* r0 = pl + (u + PY) * 132 + v0 * 8;
            float f0[10], f1[10];
            *(float4*)&f0[0] = *(const float4*)(r0);
            *(float4*)&f0[4] = *(const float4*)(r0 + 4);
            *(float2*)&f0[8] = *(const float2*)(r0 + 8);
            *(float4*)&f1[0] = *(const float4*)(r0 + 132);
            *(float4*)&f1[4] = *(const float4*)(r0 + 136);
            *(float2*)&f1[8] = *(const float2*)(r0 + 140);
            u64 P0[9], P1[9];
#pragma unroll
            for (int i = 0; i < 9; i++) {
                P0[i] = pack2(f0[i + PX], f0[i + PX]);
                P1[i] = pack2(f1[i + PX], f1[i + PX]);
            }
            const u64* wb = (const u64*)&ws[cl * 4 * 32 + cog * 8];
            u64 w00[4], w01[4], w10[4], w11[4];
#pragma unroll
            for (int cp = 0; cp < 4; cp++) {
                w00[cp] = wb[cp]; w01[cp] = wb[16 + cp];
                w10[cp] = wb[32 + cp]; w11[cp] = wb[48 + cp];
            }
#pragma unroll
            for (int j = 0; j < 8; j++) {
#pragma unroll
                for (int cp = 0; cp < 4; cp++) {
                    FFMA2(acc[cp][j], P0[j],     w00[cp]);
                    FFMA2(acc[cp][j], P0[j + 1], w01[cp]);
                    FFMA2(acc[cp][j], P1[j],     w10[cp]);
                    FFMA2(acc[cp][j], P1[j + 1], w11[cp]);
                }
            }
        }
    }
    float* o = g_t2p + (size_t)n * 32 * XP_P + (2 * u + PY + 1) * 260
             + 2 * (v0 * 8) + PX + 1;
#pragma unroll
    for (int cp = 0; cp < 4; cp++)
#pragma unroll
        for (int j = 0; j < 8; j++) {
            float2 fo = unpack2(acc[cp][j]);
            o[(cog * 8 + 2 * cp)     * XP_P + 2 * j] = fmaxf(fo.x, 0.f);
            o[(cog * 8 + 2 * cp + 1) * XP_P + 2 * j] = fmaxf(fo.y, 0.f);
        }
}

__global__ __launch_bounds__(256) void k_dect2(const float* __restrict__ w,
                                               const float* __restrict__ bias) {
    switch (blockIdx.y) {
        case 0: dect2_body<0, 0>(w, bias); break;
        case 1: dect2_body<0, 1>(w, bias); break;
        case 2: dect2_body<1, 0>(w, bias); break;
        default: dect2_body<1, 1>(w, bias); break;
    }
}

// =====================================================================
// dconv2: 3x3 p1, 32->3, sigmoid. 4 px/thread. grid 2048 x 256
// =====================================================================
__global__ __launch_bounds__(256) void k_dconv2(const float* __restrict__ w,
                                                const float* __restrict__ bias,
                                                float* __restrict__ out) {
    __shared__ u64 ws2[32 * 9 * 3];  // broadcast pairs
    for (int i = threadIdx.x; i < 32 * 9; i += 256) {
        int ci = i / 9, k = i % 9;
#pragma unroll
        for (int co = 0; co < 3; co++) {
            float wv = w[(co * 32 + ci) * 9 + k];
            ws2[i * 3 + co] = pack2(wv, wv);
        }
    }
    __syncthreads();
    int n = blockIdx.x >> 6;
    int p = ((blockIdx.x & 63) << 8) + threadIdx.x;
    int X = p & 63, oy = p >> 6;
    int ox0 = 4 * X;

    u64 acc[3][2];
#pragma unroll
    for (int co = 0; co < 3; co++) {
        float bv = bias[co];
        acc[co][0] = pack2(bv, bv);
        acc[co][1] = acc[co][0];
    }
    const float* xin = g_t2p + (size_t)n * 32 * XP_P;
#pragma unroll 2
    for (int ci = 0; ci < 32; ci++) {
        const float* pl = xin + ci * XP_P;
        float in[3][6];
#pragma unroll
        for (int ry = 0; ry < 3; ry++) {
            const float* row = pl + (oy + ry) * 260 + ox0;
            *(float4*)&in[ry][0] = *(const float4*)(row);
            *(float2*)&in[ry][4] = *(const float2*)(row + 4);
        }
        u64 pr[3][5];
#pragma unroll
        for (int ry = 0; ry < 3; ry++)
#pragma unroll
            for (int i = 0; i < 5; i++)
                pr[ry][i] = pack2(in[ry][i], in[ry][i + 1]);
#pragma unroll
        for (int ky = 0; ky < 3; ky++)
#pragma unroll
            for (int kx = 0; kx < 3; kx++) {
                const u64* wr = &ws2[(ci * 9 + ky * 3 + kx) * 3];
#pragma unroll
                for (int co = 0; co < 3; co++) {
                    FFMA2(acc[co][0], pr[ky][kx],     wr[co]);
                    FFMA2(acc[co][1], pr[ky][kx + 2], wr[co]);
                }
            }
    }
    float* o = out + (size_t)n * 3 * 65536 + oy * 256 + ox0;
#pragma unroll
    for (int co = 0; co < 3; co++) {
        float2 f0 = unpack2(acc[co][0]);
        float2 f1 = unpack2(acc[co][1]);
        o[co * 65536 + 0] = 1.f / (1.f + expf(-f0.x));
        o[co * 65536 + 1] = 1.f / (1.f + expf(-f0.y));
        o[co * 65536 + 2] = 1.f / (1.f + expf(-f1.x));
        o[co * 65536 + 3] = 1.f / (1.f + expf(-f1.y));
    }
}

// =====================================================================
extern "C" void kernel_launch(void* const* d_in, const int* in_sizes, int n_in,
                              void* d_out, int out_size) {
    const float* x       = (const float*)d_in[0];
    const float* enc_w1  = (const float*)d_in[1];
    const float* enc_b1  = (const float*)d_in[2];
    const float* enc_w2  = (const float*)d_in[3];
    const float* enc_b2  = (const float*)d_in[4];
    const float* enc_w3  = (const float*)d_in[5];
    const float* enc_b3  = (const float*)d_in[6];
    const float* codebook= (const float*)d_in[7];
    const float* dec_w1  = (const float*)d_in[8];
    const float* dec_b1  = (const float*)d_in[9];
    const float* dect_w1 = (const float*)d_in[10];
    const float* dect_b1 = (const float*)d_in[11];
    const float* dect_w2 = (const float*)d_in[12];
    const float* dect_b2 = (const float*)d_in[13];
    const float* dec_w2  = (const float*)d_in[14];
    const float* dec_b2  = (const float*)d_in[15];
    float* out = (float*)d_out;

    k_pad   <<<24576, 256>>>(x);
    k_conv1 <<<1024,  256>>>(enc_w1, enc_b1);
    k_conv2 <<<512,   256>>>(enc_w2, enc_b2);
    k_conv3 <<<512,   256>>>(enc_w3, enc_b3);
    k_vq    <<<1024,  128>>>(codebook);
    k_zq    <<<4096,  256>>>(codebook);
    k_loss  <<<1,     256>>>(out);
    k_idxout<<<512,   256>>>(out);
    k_dconv1<<<512,   256>>>(dec_w1, dec_b1);
    k_dect1 <<<dim3(512, 4),  256>>>(dect_w1, dect_b1);
    k_dect2 <<<dim3(1024, 4), 256>>>(dect_w2, dect_b2);
    k_dconv2<<<2048,  256>>>(dec_w2, dec_b2, out);
}

// round 5
// speedup vs baseline: 1.9956x; 1.0213x over previous
#include <cuda_runtime.h>
#include <math.h>

constexpr int B = 32;

typedef unsigned long long u64;
#define FFMA2(acc, v, w) \
    asm("fma.rn.f32x2 %0, %1, %2, %3;" : "=l"(acc) : "l"(v), "l"(w), "l"(acc))
__device__ __forceinline__ u64 pack2(float a, float b) {
    u64 r; asm("mov.b64 %0, {%1, %2};" : "=l"(r) : "f"(a), "f"(b)); return r;
}
__device__ __forceinline__ float2 unpack2(u64 v) {
    float2 f; asm("mov.b64 {%0, %1}, %2;" : "=f"(f.x), "=f"(f.y) : "l"(v)); return f;
}

// ---- padded planes (strides multiple of 4 floats; halos stay zero forever) ----
constexpr int XP_P = 258 * 260;   // padded input x / t2p plane
constexpr int H1_P = 130 * 132;   // h1p & t1p plane
constexpr int Z_P  = 66 * 68;     // zqp & d1p plane

__device__ float g_xp [B * 3 * XP_P];
__device__ float g_h1p[B * 32 * H1_P];
__device__ float g_h2 [B * 64 * 4096];
__device__ float g_z  [B * 8 * 4096];
__device__ float g_zqp[B * 8 * Z_P];
__device__ int   g_idx[B * 4096];
__device__ float g_part[4096];
__device__ float g_d1p[B * 64 * Z_P];
__device__ float g_t1p[B * 64 * H1_P];
__device__ float g_t2p[B * 32 * XP_P];

constexpr int XR_ELEMS = B * 3 * 65536;
constexpr int LOSS_OFF = XR_ELEMS;
constexpr int IDX_OFF  = XR_ELEMS + 1;

// =====================================================================
// pad x into g_xp interior. grid: 24576 x 256
// =====================================================================
__global__ __launch_bounds__(256) void k_pad(const float* __restrict__ x) {
    int i = blockIdx.x * 256 + threadIdx.x;
    int c = i >> 16, hw = i & 65535;
    int y = hw >> 8, xx = hw & 255;
    g_xp[(size_t)c * XP_P + (y + 1) * 260 + xx + 1] = x[i];
}

// =====================================================================
// conv1: 3->32, k4 s2 p1, 256->128, ReLU. thread: 8co x 8px. grid 1024 x 256
// =====================================================================
__global__ __launch_bounds__(256) void k_conv1(const float* __restrict__ w,
                                               const float* __restrict__ bias) {
    __shared__ float ws[48 * 32];  // [(ci*16+k)*32 + co]
    for (int i = threadIdx.x; i < 1536; i += 256) {
        int t = i >> 5, co = i & 31;
        int ci = t >> 4, k = t & 15;
        ws[i] = w[(co * 3 + ci) * 16 + k];
    }
    __syncthreads();
    int n = blockIdx.x >> 5, oyg = blockIdx.x & 31;
    int cog = threadIdx.x >> 6, oyl = (threadIdx.x >> 4) & 3, v0 = threadIdx.x & 15;
    int oy = oyg * 4 + oyl, ox0 = v0 * 8;
    u64 acc[4][8];
#pragma unroll
    for (int cp = 0; cp < 4; cp++) {
        u64 bv = pack2(bias[cog * 8 + 2 * cp], bias[cog * 8 + 2 * cp + 1]);
#pragma unroll
        for (int j = 0; j < 8; j++) acc[cp][j] = bv;
    }
    const float* xin = g_xp + (size_t)n * 3 * XP_P;
#pragma unroll 1
    for (int ci = 0; ci < 3; ci++) {
        const float* pl = xin + ci * XP_P;
#pragma unroll 1
        for (int ky = 0; ky < 4; ky++) {
            const float* row = pl + (2 * oy + ky) * 260 + 2 * ox0;
            float f[18];
            *(float4*)&f[0]  = *(const float4*)(row);
            *(float4*)&f[4]  = *(const float4*)(row + 4);
            *(float4*)&f[8]  = *(const float4*)(row + 8);
            *(float4*)&f[12] = *(const float4*)(row + 12);
            *(float2*)&f[16] = *(const float2*)(row + 16);
            u64 fb[18];
#pragma unroll
            for (int i = 0; i < 18; i++) fb[i] = pack2(f[i], f[i]);
#pragma unroll
            for (int kx = 0; kx < 4; kx++) {
                const u64* wr = (const u64*)&ws[(ci * 16 + ky * 4 + kx) * 32 + cog * 8];
                u64 w0 = wr[0], w1 = wr[1], w2 = wr[2], w3 = wr[3];
#pragma unroll
                for (int j = 0; j < 8; j++) {
                    u64 vv = fb[2 * j + kx];
                    FFMA2(acc[0][j], vv, w0); FFMA2(acc[1][j], vv, w1);
                    FFMA2(acc[2][j], vv, w2); FFMA2(acc[3][j], vv, w3);
                }
            }
        }
    }
    float* o = g_h1p + (size_t)n * 32 * H1_P + (oy + 1) * 132 + ox0 + 1;
#pragma unroll
    for (int cp = 0; cp < 4; cp++)
#pragma unroll
        for (int j = 0; j < 8; j++) {
            float2 fo = unpack2(acc[cp][j]);
            o[(cog * 8 + 2 * cp)     * H1_P + j] = fmaxf(fo.x, 0.f);
            o[(cog * 8 + 2 * cp + 1) * H1_P + j] = fmaxf(fo.y, 0.f);
        }
}

// =====================================================================
// conv2: 32->64, k4 s2 p1, 128->64, ReLU. thread: 8co x 8px. grid 512 x 256
// =====================================================================
__global__ __launch_bounds__(256) void k_conv2(const float* __restrict__ w,
                                               const float* __restrict__ bias) {
    __shared__ float ws[8 * 16 * 64];  // 32KB
    int n = blockIdx.x >> 4, oyg = blockIdx.x & 15;
    int cog = threadIdx.x >> 5, oyl = (threadIdx.x >> 3) & 3, v0 = threadIdx.x & 7;
    int oy = oyg * 4 + oyl, ox0 = v0 * 8;
    u64 acc[4][8];
#pragma unroll
    for (int cp = 0; cp < 4; cp++) {
        u64 bv = pack2(bias[cog * 8 + 2 * cp], bias[cog * 8 + 2 * cp + 1]);
#pragma unroll
        for (int j = 0; j < 8; j++) acc[cp][j] = bv;
    }
    const float* xin = g_h1p + (size_t)n * 32 * H1_P;
#pragma unroll 1
    for (int cc = 0; cc < 4; cc++) {
        __syncthreads();
        for (int i = threadIdx.x; i < 8192; i += 256) {
            int t = i >> 6, co = i & 63;
            int cl = t >> 4, k = t & 15;
            ws[i] = w[(co * 32 + cc * 8 + cl) * 16 + k];
        }
        __syncthreads();
#pragma unroll 1
        for (int cl = 0; cl < 8; cl++) {
            const float* pl = xin + (cc * 8 + cl) * H1_P;
#pragma unroll 1
            for (int ky = 0; ky < 4; ky++) {
                const float* row = pl + (2 * oy + ky) * 132 + 2 * ox0;
                float f[18];
                *(float4*)&f[0]  = *(const float4*)(row);
                *(float4*)&f[4]  = *(const float4*)(row + 4);
                *(float4*)&f[8]  = *(const float4*)(row + 8);
                *(float4*)&f[12] = *(const float4*)(row + 12);
                *(float2*)&f[16] = *(const float2*)(row + 16);
                u64 fb[18];
#pragma unroll
                for (int i = 0; i < 18; i++) fb[i] = pack2(f[i], f[i]);
#pragma unroll
                for (int kx = 0; kx < 4; kx++) {
                    const u64* wr = (const u64*)&ws[(cl * 16 + ky * 4 + kx) * 64 + cog * 8];
                    u64 w0 = wr[0], w1 = wr[1], w2 = wr[2], w3 = wr[3];
#pragma unroll
                    for (int j = 0; j < 8; j++) {
                        u64 vv = fb[2 * j + kx];
                        FFMA2(acc[0][j], vv, w0); FFMA2(acc[1][j], vv, w1);
                        FFMA2(acc[2][j], vv, w2); FFMA2(acc[3][j], vv, w3);
                    }
                }
            }
        }
    }
    float* o = g_h2 + (size_t)n * 64 * 4096 + oy * 64 + ox0;
#pragma unroll
    for (int cp = 0; cp < 4; cp++)
#pragma unroll
        for (int j = 0; j < 8; j++) {
            float2 fo = unpack2(acc[cp][j]);
            o[(cog * 8 + 2 * cp)     * 4096 + j] = fmaxf(fo.x, 0.f);
            o[(cog * 8 + 2 * cp + 1) * 4096 + j] = fmaxf(fo.y, 0.f);
        }
}

// =====================================================================
// conv3: 1x1, 64->8. grid: 512 x 256
// =====================================================================
__global__ __launch_bounds__(256) void k_conv3(const float* __restrict__ w,
                                               const float* __restrict__ bias) {
    __shared__ float ws[64 * 8];
    for (int i = threadIdx.x; i < 512; i += 256) {
        int ci = i >> 3, co = i & 7;
        ws[i] = w[co * 64 + ci];
    }
    __syncthreads();
    int n = blockIdx.x >> 4;
    int p = ((blockIdx.x & 15) << 8) + threadIdx.x;
    u64 acc[4];
#pragma unroll
    for (int c = 0; c < 4; c++) acc[c] = pack2(bias[2 * c], bias[2 * c + 1]);
    const float* xin = g_h2 + (size_t)n * 64 * 4096;
#pragma unroll 8
    for (int ci = 0; ci < 64; ci++) {
        float v = xin[ci * 4096 + p];
        u64 vv = pack2(v, v);
        const u64* wr = (const u64*)&ws[ci * 8];
#pragma unroll
        for (int c = 0; c < 4; c++) FFMA2(acc[c], vv, wr[c]);
    }
    float* o = g_z + (size_t)n * 8 * 4096;
#pragma unroll
    for (int c = 0; c < 4; c++) {
        float2 f = unpack2(acc[c]);
        o[(2 * c)     * 4096 + p] = f.x;
        o[(2 * c + 1) * 4096 + p] = f.y;
    }
}

// =====================================================================
// VQ argmin. grid: 1024 x 128
// =====================================================================
__global__ __launch_bounds__(128) void k_vq(const float* __restrict__ cb) {
    __shared__ float cs[512 * 8];
    __shared__ float csq[512];
    for (int i = threadIdx.x; i < 4096; i += 128) cs[i] = cb[i];
    __syncthreads();
    for (int k = threadIdx.x; k < 512; k += 128) {
        float s = 0.f;
#pragma unroll
        for (int d = 0; d < 8; d++) { float c = cs[k * 8 + d]; s += c * c; }
        csq[k] = s;
    }
    __syncthreads();
    int p = blockIdx.x * 128 + threadIdx.x;
    int n = p >> 12, hw = p & 4095;
    const float* zp = g_z + (size_t)n * 8 * 4096 + hw;
    float zv[8]; float zsq = 0.f;
#pragma unroll
    for (int d = 0; d < 8; d++) { zv[d] = zp[d * 4096]; zsq += zv[d] * zv[d]; }
    float best = 3.4e38f; int bi = 0;
    for (int k = 0; k < 512; k++) {
        float dot = 0.f;
#pragma unroll
        for (int d = 0; d < 8; d++) dot = fmaf(zv[d], cs[k * 8 + d], dot);
        float dist = zsq + csq[k] - 2.f * dot;
        if (dist < best) { best = dist; bi = k; }
    }
    g_idx[p] = bi;
}

// =====================================================================
// z_q gather (faithful layout bug) + loss partials. grid: 4096 x 256
// =====================================================================
__global__ __launch_bounds__(256) void k_zq(const float* __restrict__ cb) {
    int i = blockIdx.x * 256 + threadIdx.x;
    float q = cb[g_idx[i >> 3] * 8 + (i & 7)];
    int n = i >> 15, c = (i >> 12) & 7, hw = i & 4095;
    int y = hw >> 6, xx = hw & 63;
    g_zqp[(size_t)(n * 8 + c) * Z_P + (y + 1) * 68 + xx + 1] = q;
    float diff = g_z[i] - q;
    float v = diff * diff;
    __shared__ float red[256];
    red[threadIdx.x] = v; __syncthreads();
    for (int s = 128; s > 0; s >>= 1) {
        if (threadIdx.x < s) red[threadIdx.x] += red[threadIdx.x + s];
        __syncthreads();
    }
    if (threadIdx.x == 0) g_part[blockIdx.x] = red[0];
}

__global__ __launch_bounds__(256) void k_loss(float* __restrict__ out) {
    __shared__ float red[256];
    float s = 0.f;
    for (int i = threadIdx.x; i < 4096; i += 256) s += g_part[i];
    red[threadIdx.x] = s; __syncthreads();
    for (int st = 128; st > 0; st >>= 1) {
        if (threadIdx.x < st) red[threadIdx.x] += red[threadIdx.x + st];
        __syncthreads();
    }
    if (threadIdx.x == 0) out[LOSS_OFF] = red[0] * (1.25f / 1048576.f);
}

__global__ __launch_bounds__(256) void k_idxout(float* __restrict__ out) {
    int p = blockIdx.x * 256 + threadIdx.x;
    if (p < B * 4096) out[IDX_OFF + p] = (float)g_idx[p];
}

// =====================================================================
// dconv1: 3x3 p1, 8->64, ReLU. thread: 8co x 8px. grid 512 x 256
// =====================================================================
__global__ __launch_bounds__(256) void k_dconv1(const float* __restrict__ w,
                                                const float* __restrict__ bias) {
    __shared__ float ws[8 * 9 * 64];  // [(ci*9+k)*64 + co]
    for (int i = threadIdx.x; i < 4608; i += 256) {
        int t = i >> 6, co = i & 63;
        int ci = t / 9, k = t % 9;
        ws[i] = w[(co * 8 + ci) * 9 + k];
    }
    __syncthreads();
    int n = blockIdx.x >> 4, oyg = blockIdx.x & 15;
    int cog = threadIdx.x >> 5, oyl = (threadIdx.x >> 3) & 3, v0 = threadIdx.x & 7;
    int oy = oyg * 4 + oyl, ox0 = v0 * 8;
    u64 acc[4][8];
#pragma unroll
    for (int cp = 0; cp < 4; cp++) {
        u64 bv = pack2(bias[cog * 8 + 2 * cp], bias[cog * 8 + 2 * cp + 1]);
#pragma unroll
        for (int j = 0; j < 8; j++) acc[cp][j] = bv;
    }
    const float* xin = g_zqp + (size_t)n * 8 * Z_P;
#pragma unroll 1
    for (int ci = 0; ci < 8; ci++) {
        const float* pl = xin + ci * Z_P;
#pragma unroll 1
        for (int ky = 0; ky < 3; ky++) {
            const float* row = pl + (oy + ky) * 68 + ox0;
            float f[10];
            *(float4*)&f[0] = *(const float4*)(row);
            *(float4*)&f[4] = *(const float4*)(row + 4);
            *(float2*)&f[8] = *(const float2*)(row + 8);
            u64 fb[10];
#pragma unroll
            for (int i = 0; i < 10; i++) fb[i] = pack2(f[i], f[i]);
#pragma unroll
            for (int kx = 0; kx < 3; kx++) {
                const u64* wr = (const u64*)&ws[(ci * 9 + ky * 3 + kx) * 64 + cog * 8];
                u64 w0 = wr[0], w1 = wr[1], w2 = wr[2], w3 = wr[3];
#pragma unroll
                for (int j = 0; j < 8; j++) {
                    u64 vv = fb[j + kx];
                    FFMA2(acc[0][j], vv, w0); FFMA2(acc[1][j], vv, w1);
                    FFMA2(acc[2][j], vv, w2); FFMA2(acc[3][j], vv, w3);
                }
            }
        }
    }
    float* o = g_d1p + (size_t)n * 64 * Z_P + (oy + 1) * 68 + ox0 + 1;
#pragma unroll
    for (int cp = 0; cp < 4; cp++)
#pragma unroll
        for (int j = 0; j < 8; j++) {
            float2 fo = unpack2(acc[cp][j]);
            o[(cog * 8 + 2 * cp)     * Z_P + j] = fmaxf(fo.x, 0.f);
            o[(cog * 8 + 2 * cp + 1) * Z_P + j] = fmaxf(fo.y, 0.f);
        }
}

// =====================================================================
// dect1: 64->64, k4 s2 p1, 64->128, ReLU. parity sub-conv, compile-time (PY,PX).
// thread: 8co x 8v. grid (512, 4) x 256
// =====================================================================
template<int PY, int PX>
__device__ __forceinline__ void dect1_body(const float* __restrict__ w,
                                           const float* __restrict__ bias) {
    __shared__ float ws[16 * 4 * 64];  // [(cl*4+dy*2+dx)*64 + co], 16KB
    int n = blockIdx.x >> 4, ug = blockIdx.x & 15;
    int cog = threadIdx.x >> 5, ul = (threadIdx.x >> 3) & 3, v0 = threadIdx.x & 7;
    int u = ug * 4 + ul;
    u64 acc[4][8];
#pragma unroll
    for (int cp = 0; cp < 4; cp++) {
        u64 bv = pack2(bias[cog * 8 + 2 * cp], bias[cog * 8 + 2 * cp + 1]);
#pragma unroll
        for (int j = 0; j < 8; j++) acc[cp][j] = bv;
    }
    const float* xin = g_d1p + (size_t)n * 64 * Z_P;
#pragma unroll 1
    for (int cc = 0; cc < 4; cc++) {
        __syncthreads();
        for (int i = threadIdx.x; i < 4096; i += 256) {
            int co = i & 63, t = i >> 6;
            int cl = t >> 2, tp = t & 3;
            ws[i] = w[(co * 64 + cc * 16 + cl) * 16
                      + (PY + 2 * (tp >> 1)) * 4 + PX + 2 * (tp & 1)];
        }
        __syncthreads();
#pragma unroll 1
        for (int cl = 0; cl < 16; cl++) {
            const float* pl = xin + (cc * 16 + cl) * Z_P;
            const float* r0 = pl + (u + PY) * 68 + v0 * 8;
            float f0[10], f1[10];
            *(float4*)&f0[0] = *(const float4*)(r0);
            *(float4*)&f0[4] = *(const float4*)(r0 + 4);
            *(float2*)&f0[8] = *(const float2*)(r0 + 8);
            *(float4*)&f1[0] = *(const float4*)(r0 + 68);
            *(float4*)&f1[4] = *(const float4*)(r0 + 72);
            *(float2*)&f1[8] = *(const float2*)(r0 + 76);
            u64 P0[9], P1[9];
#pragma unroll
            for (int i = 0; i < 9; i++) {
                P0[i] = pack2(f0[i + PX], f0[i + PX]);
                P1[i] = pack2(f1[i + PX], f1[i + PX]);
            }
            const u64* wb = (const u64*)&ws[cl * 4 * 64 + cog * 8];
            u64 w00[4], w01[4], w10[4], w11[4];
#pragma unroll
            for (int cp = 0; cp < 4; cp++) {
                w00[cp] = wb[cp]; w01[cp] = wb[32 + cp];
                w10[cp] = wb[64 + cp]; w11[cp] = wb[96 + cp];
            }
#pragma unroll
            for (int j = 0; j < 8; j++) {
#pragma unroll
                for (int cp = 0; cp < 4; cp++) {
                    FFMA2(acc[cp][j], P0[j],     w00[cp]);
                    FFMA2(acc[cp][j], P0[j + 1], w01[cp]);
                    FFMA2(acc[cp][j], P1[j],     w10[cp]);
                    FFMA2(acc[cp][j], P1[j + 1], w11[cp]);
                }
            }
        }
    }
    float* o = g_t1p + (size_t)n * 64 * H1_P + (2 * u + PY + 1) * 132
             + 2 * (v0 * 8) + PX + 1;
#pragma unroll
    for (int cp = 0; cp < 4; cp++)
#pragma unroll
        for (int j = 0; j < 8; j++) {
            float2 fo = unpack2(acc[cp][j]);
            o[(cog * 8 + 2 * cp)     * H1_P + 2 * j] = fmaxf(fo.x, 0.f);
            o[(cog * 8 + 2 * cp + 1) * H1_P + 2 * j] = fmaxf(fo.y, 0.f);
        }
}

__global__ __launch_bounds__(256) void k_dect1(const float* __restrict__ w,
                                               const float* __restrict__ bias) {
    switch (blockIdx.y) {
        case 0: dect1_body<0, 0>(w, bias); break;
        case 1: dect1_body<0, 1>(w, bias); break;
        case 2: dect1_body<1, 0>(w, bias); break;
        default: dect1_body<1, 1>(w, bias); break;
    }
}

// =====================================================================
// dect2: 64->32, k4 s2 p1, 128->256, ReLU. thread: 8co x 8v. grid (1024,4) x 256
// =====================================================================
template<int PY, int PX>
__device__ __forceinline__ void dect2_body(const float* __restrict__ w,
                                           const float* __restrict__ bias) {
    __shared__ float ws[32 * 4 * 32];  // [(cl*4+dy*2+dx)*32 + co], 16KB
    int n = blockIdx.x >> 5, ug = blockIdx.x & 31;
    int cog = threadIdx.x >> 6, ul = (threadIdx.x >> 4) & 3, v0 = threadIdx.x & 15;
    int u = ug * 4 + ul;
    u64 acc[4][8];
#pragma unroll
    for (int cp = 0; cp < 4; cp++) {
        u64 bv = pack2(bias[cog * 8 + 2 * cp], bias[cog * 8 + 2 * cp + 1]);
#pragma unroll
        for (int j = 0; j < 8; j++) acc[cp][j] = bv;
    }
    const float* xin = g_t1p + (size_t)n * 64 * H1_P;
#pragma unroll 1
    for (int cc = 0; cc < 2; cc++) {
        __syncthreads();
        for (int i = threadIdx.x; i < 4096; i += 256) {
            int co = i & 31, t = i >> 5;
            int cl = t >> 2, tp = t & 3;
            ws[i] = w[(co * 64 + cc * 32 + cl) * 16
                      + (PY + 2 * (tp >> 1)) * 4 + PX + 2 * (tp & 1)];
        }
        __syncthreads();
#pragma unroll 1
        for (int cl = 0; cl < 32; cl++) {
            const float* pl = xin + (cc * 32 + cl) * H1_P;
            const float* r0 = pl + (u + PY) * 132 + v0 * 8;
            float f0[10], f1[10];
            *(float4*)&f0[0] = *(const float4*)(r0);
            *(float4*)&f0[4] = *(const float4*)(r0 + 4);
            *(float2*)&f0[8] = *(const float2*)(r0 + 8);
            *(float4*)&f1[0] = *(const float4*)(r0 + 132);
            *(float4*)&f1[4] = *(const float4*)(r0 + 136);
            *(float2*)&f1[8] = *(const float2*)(r0 + 140);
            u64 P0[9], P1[9];
#pragma unroll
            for (int i = 0; i < 9; i++) {
                P0[i] = pack2(f0[i + PX], f0[i + PX]);
                P1[i] = pack2(f1[i + PX], f1[i + PX]);
            }
            const u64* wb = (const u64*)&ws[cl * 4 * 32 + cog * 8];
            u64 w00[4], w01[4], w10[4], w11[4];
#pragma unroll
            for (int cp = 0; cp < 4; cp++) {
                w00[cp] = wb[cp]; w01[cp] = wb[16 + cp];
                w10[cp] = wb[32 + cp]; w11[cp] = wb[48 + cp];
            }
#pragma unroll
            for (int j = 0; j < 8; j++) {
#pragma unroll
                for (int cp = 0; cp < 4; cp++) {
                    FFMA2(acc[cp][j], P0[j],     w00[cp]);
                    FFMA2(acc[cp][j], P0[j + 1], w01[cp]);
                    FFMA2(acc[cp][j], P1[j],     w10[cp]);
                    FFMA2(acc[cp][j], P1[j + 1], w11[cp]);
                }
            }
        }
    }
    float* o = g_t2p + (size_t)n * 32 * XP_P + (2 * u + PY + 1) * 260
             + 2 * (v0 * 8) + PX + 1;
#pragma unroll
    for (int cp = 0; cp < 4; cp++)
#pragma unroll
        for (int j = 0; j < 8; j++) {
            float2 fo = unpack2(acc[cp][j]);
            o[(cog * 8 + 2 * cp)     * XP_P + 2 * j] = fmaxf(fo.x, 0.f);
            o[(cog * 8 + 2 * cp + 1) * XP_P + 2 * j] = fmaxf(fo.y, 0.f);
        }
}

__global__ __launch_bounds__(256) void k_dect2(const float* __restrict__ w,
                                               const float* __restrict__ bias) {
    switch (blockIdx.y) {
        case 0: dect2_body<0, 0>(w, bias); break;
        case 1: dect2_body<0, 1>(w, bias); break;
        case 2: dect2_body<1, 0>(w, bias); break;
        default: dect2_body<1, 1>(w, bias); break;
    }
}

// =====================================================================
// dconv2: 3x3 p1, 32->3, sigmoid. 4 px/thread. grid 2048 x 256
// =====================================================================
__global__ __launch_bounds__(256) void k_dconv2(const float* __restrict__ w,
                                                const float* __restrict__ bias,
                                                float* __restrict__ out) {
    __shared__ u64 ws2[32 * 9 * 3];  // broadcast pairs
    for (int i = threadIdx.x; i < 32 * 9; i += 256) {
        int ci = i / 9, k = i % 9;
#pragma unroll
        for (int co = 0; co < 3; co++) {
            float wv = w[(co * 32 + ci) * 9 + k];
            ws2[i * 3 + co] = pack2(wv, wv);
        }
    }
    __syncthreads();
    int n = blockIdx.x >> 6;
    int p = ((blockIdx.x & 63) << 8) + threadIdx.x;
    int X = p & 63, oy = p >> 6;
    int ox0 = 4 * X;

    u64 acc[3][2];
#pragma unroll
    for (int co = 0; co < 3; co++) {
        float bv = bias[co];
        acc[co][0] = pack2(bv, bv);
        acc[co][1] = acc[co][0];
    }
    const float* xin = g_t2p + (size_t)n * 32 * XP_P;
#pragma unroll 1
    for (int ci = 0; ci < 32; ci++) {
        const float* pl = xin + ci * XP_P;
        float in[3][6];
#pragma unroll
        for (int ry = 0; ry < 3; ry++) {
            const float* row = pl + (oy + ry) * 260 + ox0;
            *(float4*)&in[ry][0] = *(const float4*)(row);
            *(float2*)&in[ry][4] = *(const float2*)(row + 4);
        }
        u64 pr[3][5];
#pragma unroll
        for (int ry = 0; ry < 3; ry++)
#pragma unroll
            for (int i = 0; i < 5; i++)
                pr[ry][i] = pack2(in[ry][i], in[ry][i + 1]);
#pragma unroll
        for (int ky = 0; ky < 3; ky++)
#pragma unroll
            for (int kx = 0; kx < 3; kx++) {
                const u64* wr = &ws2[(ci * 9 + ky * 3 + kx) * 3];
#pragma unroll
                for (int co = 0; co < 3; co++) {
                    FFMA2(acc[co][0], pr[ky][kx],     wr[co]);
                    FFMA2(acc[co][1], pr[ky][kx + 2], wr[co]);
                }
            }
    }
    float* o = out + (size_t)n * 3 * 65536 + oy * 256 + ox0;
#pragma unroll
    for (int co = 0; co < 3; co++) {
        float2 f0 = unpack2(acc[co][0]);
        float2 f1 = unpack2(acc[co][1]);
        o[co * 65536 + 0] = 1.f / (1.f + expf(-f0.x));
        o[co * 65536 + 1] = 1.f / (1.f + expf(-f0.y));
        o[co * 65536 + 2] = 1.f / (1.f + expf(-f1.x));
        o[co * 65536 + 3] = 1.f / (1.f + expf(-f1.y));
    }
}

// =====================================================================
extern "C" void kernel_launch(void* const* d_in, const int* in_sizes, int n_in,
                              void* d_out, int out_size) {
    const float* x       = (const float*)d_in[0];
    const float* enc_w1  = (const float*)d_in[1];
    const float* enc_b1  = (const float*)d_in[2];
    const float* enc_w2  = (const float*)d_in[3];
    const float* enc_b2  = (const float*)d_in[4];
    const float* enc_w3  = (const float*)d_in[5];
    const float* enc_b3  = (const float*)d_in[6];
    const float* codebook= (const float*)d_in[7];
    const float* dec_w1  = (const float*)d_in[8];
    const float* dec_b1  = (const float*)d_in[9];
    const float* dect_w1 = (const float*)d_in[10];
    const float* dect_b1 = (const float*)d_in[11];
    const float* dect_w2 = (const float*)d_in[12];
    const float* dect_b2 = (const float*)d_in[13];
    const float* dec_w2  = (const float*)d_in[14];
    const float* dec_b2  = (const float*)d_in[15];
    float* out = (float*)d_out;

    k_pad   <<<24576, 256>>>(x);
    k_conv1 <<<1024,  256>>>(enc_w1, enc_b1);
    k_conv2 <<<512,   256>>>(enc_w2, enc_b2);
    k_conv3 <<<512,   256>>>(enc_w3, enc_b3);
    k_vq    <<<1024,  128>>>(codebook);
    k_zq    <<<4096,  256>>>(codebook);
    k_loss  <<<1,     256>>>(out);
    k_idxout<<<512,   256>>>(out);
    k_dconv1<<<512,   256>>>(dec_w1, dec_b1);
    k_dect1 <<<dim3(512, 4),  256>>>(dect_w1, dect_b1);
    k_dect2 <<<dim3(1024, 4), 256>>>(dect_w2, dect_b2);
    k_dconv2<<<2048,  256>>>(dec_w2, dec_b2, out);
}

// round 6
// speedup vs baseline: 2.0007x; 1.0026x over previous
#include <cuda_runtime.h>
#include <math.h>

constexpr int B = 32;

typedef unsigned long long u64;
#define FFMA2(acc, v, w) \
    asm("fma.rn.f32x2 %0, %1, %2, %3;" : "=l"(acc) : "l"(v), "l"(w), "l"(acc))
__device__ __forceinline__ u64 pack2(float a, float b) {
    u64 r; asm("mov.b64 %0, {%1, %2};" : "=l"(r) : "f"(a), "f"(b)); return r;
}
__device__ __forceinline__ float2 unpack2(u64 v) {
    float2 f; asm("mov.b64 {%0, %1}, %2;" : "=f"(f.x), "=f"(f.y) : "l"(v)); return f;
}

// ---- padded planes (strides multiple of 4 floats; halos stay zero forever) ----
constexpr int XP_P = 258 * 260;
constexpr int H1_P = 130 * 132;
constexpr int Z_P  = 66 * 68;

__device__ float g_xp [B * 3 * XP_P];
__device__ float g_h1p[B * 32 * H1_P];
__device__ float g_h2 [B * 64 * 4096];
__device__ float g_z  [B * 8 * 4096];
__device__ float g_zqp[B * 8 * Z_P];
__device__ int   g_idx[B * 4096];
__device__ float g_part[4096];
__device__ float g_d1p[B * 64 * Z_P];
__device__ float g_t1p[B * 64 * H1_P];
__device__ float g_t2p[B * 32 * XP_P];

constexpr int XR_ELEMS = B * 3 * 65536;
constexpr int LOSS_OFF = XR_ELEMS;
constexpr int IDX_OFF  = XR_ELEMS + 1;

// 18-float strip (for k4s2 convs)
struct S18 { float4 a, b, c, d; float2 e; };
__device__ __forceinline__ S18 ld18(const float* r) {
    S18 s;
    s.a = *(const float4*)(r);      s.b = *(const float4*)(r + 4);
    s.c = *(const float4*)(r + 8);  s.d = *(const float4*)(r + 12);
    s.e = *(const float2*)(r + 16);
    return s;
}
__device__ __forceinline__ void unp18(const S18& s, float* f) {
    *(float4*)&f[0] = s.a; *(float4*)&f[4] = s.b;
    *(float4*)&f[8] = s.c; *(float4*)&f[12] = s.d;
    *(float2*)&f[16] = s.e;
}
// 10-float strip (for stride-1 / parity convs)
struct S10 { float4 a, b; float2 c; };
__device__ __forceinline__ S10 ld10(const float* r) {
    S10 s;
    s.a = *(const float4*)(r); s.b = *(const float4*)(r + 4);
    s.c = *(const float2*)(r + 8);
    return s;
}
__device__ __forceinline__ void unp10(const S10& s, float* f) {
    *(float4*)&f[0] = s.a; *(float4*)&f[4] = s.b; *(float2*)&f[8] = s.c;
}

// =====================================================================
// pad x. grid: 24576 x 256
// =====================================================================
__global__ __launch_bounds__(256) void k_pad(const float* __restrict__ x) {
    int i = blockIdx.x * 256 + threadIdx.x;
    int c = i >> 16, hw = i & 65535;
    int y = hw >> 8, xx = hw & 255;
    g_xp[(size_t)c * XP_P + (y + 1) * 260 + xx + 1] = x[i];
}

// =====================================================================
// conv1: 3->32, k4 s2 p1, 256->128, ReLU. 8co x 8px. grid 1024 x 256
// pipelined over idx = ci*4+ky (12 iters)
// =====================================================================
__global__ __launch_bounds__(256) void k_conv1(const float* __restrict__ w,
                                               const float* __restrict__ bias) {
    __shared__ float ws[48 * 32];
    for (int i = threadIdx.x; i < 1536; i += 256) {
        int t = i >> 5, co = i & 31;
        int ci = t >> 4, k = t & 15;
        ws[i] = w[(co * 3 + ci) * 16 + k];
    }
    __syncthreads();
    int n = blockIdx.x >> 5, oyg = blockIdx.x & 31;
    int cog = threadIdx.x >> 6, oyl = (threadIdx.x >> 4) & 3, v0 = threadIdx.x & 15;
    int oy = oyg * 4 + oyl, ox0 = v0 * 8;
    u64 acc[4][8];
#pragma unroll
    for (int cp = 0; cp < 4; cp++) {
        u64 bv = pack2(bias[cog * 8 + 2 * cp], bias[cog * 8 + 2 * cp + 1]);
#pragma unroll
        for (int j = 0; j < 8; j++) acc[cp][j] = bv;
    }
    const float* base = g_xp + (size_t)n * 3 * XP_P + 2 * oy * 260 + 2 * ox0;
    S18 cur = ld18(base);
#pragma unroll 1
    for (int idx = 0; idx < 12; idx++) {
        int nx = idx < 11 ? idx + 1 : 11;
        S18 nxt = ld18(base + (nx >> 2) * XP_P + (nx & 3) * 260);
        float f[18]; unp18(cur, f);
        u64 fb[18];
#pragma unroll
        for (int i = 0; i < 18; i++) fb[i] = pack2(f[i], f[i]);
        int ci = idx >> 2, ky = idx & 3;
#pragma unroll
        for (int kx = 0; kx < 4; kx++) {
            const u64* wr = (const u64*)&ws[(ci * 16 + ky * 4 + kx) * 32 + cog * 8];
            u64 w0 = wr[0], w1 = wr[1], w2 = wr[2], w3 = wr[3];
#pragma unroll
            for (int j = 0; j < 8; j++) {
                u64 vv = fb[2 * j + kx];
                FFMA2(acc[0][j], vv, w0); FFMA2(acc[1][j], vv, w1);
                FFMA2(acc[2][j], vv, w2); FFMA2(acc[3][j], vv, w3);
            }
        }
        cur = nxt;
    }
    float* o = g_h1p + (size_t)n * 32 * H1_P + (oy + 1) * 132 + ox0 + 1;
#pragma unroll
    for (int cp = 0; cp < 4; cp++)
#pragma unroll
        for (int j = 0; j < 8; j++) {
            float2 fo = unpack2(acc[cp][j]);
            o[(cog * 8 + 2 * cp)     * H1_P + j] = fmaxf(fo.x, 0.f);
            o[(cog * 8 + 2 * cp + 1) * H1_P + j] = fmaxf(fo.y, 0.f);
        }
}

// =====================================================================
// conv2: 32->64, k4 s2 p1, 128->64, ReLU. 8co x 8px. grid 512 x 256
// pipelined over idx = cl*4+ky (32 iters per cc chunk)
// =====================================================================
__global__ __launch_bounds__(256) void k_conv2(const float* __restrict__ w,
                                               const float* __restrict__ bias) {
    __shared__ float ws[8 * 16 * 64];
    int n = blockIdx.x >> 4, oyg = blockIdx.x & 15;
    int cog = threadIdx.x >> 5, oyl = (threadIdx.x >> 3) & 3, v0 = threadIdx.x & 7;
    int oy = oyg * 4 + oyl, ox0 = v0 * 8;
    u64 acc[4][8];
#pragma unroll
    for (int cp = 0; cp < 4; cp++) {
        u64 bv = pack2(bias[cog * 8 + 2 * cp], bias[cog * 8 + 2 * cp + 1]);
#pragma unroll
        for (int j = 0; j < 8; j++) acc[cp][j] = bv;
    }
    const float* xin = g_h1p + (size_t)n * 32 * H1_P + 2 * oy * 132 + 2 * ox0;
#pragma unroll 1
    for (int cc = 0; cc < 4; cc++) {
        __syncthreads();
        for (int i = threadIdx.x; i < 8192; i += 256) {
            int t = i >> 6, co = i & 63;
            int cl = t >> 4, k = t & 15;
            ws[i] = w[(co * 32 + cc * 8 + cl) * 16 + k];
        }
        __syncthreads();
        const float* base = xin + cc * 8 * H1_P;
        S18 cur = ld18(base);
#pragma unroll 1
        for (int idx = 0; idx < 32; idx++) {
            int nx = idx < 31 ? idx + 1 : 31;
            S18 nxt = ld18(base + (nx >> 2) * H1_P + (nx & 3) * 132);
            float f[18]; unp18(cur, f);
            u64 fb[18];
#pragma unroll
            for (int i = 0; i < 18; i++) fb[i] = pack2(f[i], f[i]);
            int cl = idx >> 2, ky = idx & 3;
#pragma unroll
            for (int kx = 0; kx < 4; kx++) {
                const u64* wr = (const u64*)&ws[(cl * 16 + ky * 4 + kx) * 64 + cog * 8];
                u64 w0 = wr[0], w1 = wr[1], w2 = wr[2], w3 = wr[3];
#pragma unroll
                for (int j = 0; j < 8; j++) {
                    u64 vv = fb[2 * j + kx];
                    FFMA2(acc[0][j], vv, w0); FFMA2(acc[1][j], vv, w1);
                    FFMA2(acc[2][j], vv, w2); FFMA2(acc[3][j], vv, w3);
                }
            }
            cur = nxt;
        }
    }
    float* o = g_h2 + (size_t)n * 64 * 4096 + oy * 64 + ox0;
#pragma unroll
    for (int cp = 0; cp < 4; cp++)
#pragma unroll
        for (int j = 0; j < 8; j++) {
            float2 fo = unpack2(acc[cp][j]);
            o[(cog * 8 + 2 * cp)     * 4096 + j] = fmaxf(fo.x, 0.f);
            o[(cog * 8 + 2 * cp + 1) * 4096 + j] = fmaxf(fo.y, 0.f);
        }
}

// =====================================================================
// conv3: 1x1, 64->8. grid: 512 x 256
// =====================================================================
__global__ __launch_bounds__(256) void k_conv3(const float* __restrict__ w,
                                               const float* __restrict__ bias) {
    __shared__ float ws[64 * 8];
    for (int i = threadIdx.x; i < 512; i += 256) {
        int ci = i >> 3, co = i & 7;
        ws[i] = w[co * 64 + ci];
    }
    __syncthreads();
    int n = blockIdx.x >> 4;
    int p = ((blockIdx.x & 15) << 8) + threadIdx.x;
    u64 acc[4];
#pragma unroll
    for (int c = 0; c < 4; c++) acc[c] = pack2(bias[2 * c], bias[2 * c + 1]);
    const float* xin = g_h2 + (size_t)n * 64 * 4096;
#pragma unroll 8
    for (int ci = 0; ci < 64; ci++) {
        float v = xin[ci * 4096 + p];
        u64 vv = pack2(v, v);
        const u64* wr = (const u64*)&ws[ci * 8];
#pragma unroll
        for (int c = 0; c < 4; c++) FFMA2(acc[c], vv, wr[c]);
    }
    float* o = g_z + (size_t)n * 8 * 4096;
#pragma unroll
    for (int c = 0; c < 4; c++) {
        float2 f = unpack2(acc[c]);
        o[(2 * c)     * 4096 + p] = f.x;
        o[(2 * c + 1) * 4096 + p] = f.y;
    }
}

// =====================================================================
// VQ argmin. grid: 1024 x 128
// =====================================================================
__global__ __launch_bounds__(128) void k_vq(const float* __restrict__ cb) {
    __shared__ float cs[512 * 8];
    __shared__ float csq[512];
    for (int i = threadIdx.x; i < 4096; i += 128) cs[i] = cb[i];
    __syncthreads();
    for (int k = threadIdx.x; k < 512; k += 128) {
        float s = 0.f;
#pragma unroll
        for (int d = 0; d < 8; d++) { float c = cs[k * 8 + d]; s += c * c; }
        csq[k] = s;
    }
    __syncthreads();
    int p = blockIdx.x * 128 + threadIdx.x;
    int n = p >> 12, hw = p & 4095;
    const float* zp = g_z + (size_t)n * 8 * 4096 + hw;
    float zv[8]; float zsq = 0.f;
#pragma unroll
    for (int d = 0; d < 8; d++) { zv[d] = zp[d * 4096]; zsq += zv[d] * zv[d]; }
    float best = 3.4e38f; int bi = 0;
    for (int k = 0; k < 512; k++) {
        float dot = 0.f;
#pragma unroll
        for (int d = 0; d < 8; d++) dot = fmaf(zv[d], cs[k * 8 + d], dot);
        float dist = zsq + csq[k] - 2.f * dot;
        if (dist < best) { best = dist; bi = k; }
    }
    g_idx[p] = bi;
}

// =====================================================================
// z_q gather + loss partials. grid: 4096 x 256
// =====================================================================
__global__ __launch_bounds__(256) void k_zq(const float* __restrict__ cb) {
    int i = blockIdx.x * 256 + threadIdx.x;
    float q = cb[g_idx[i >> 3] * 8 + (i & 7)];
    int n = i >> 15, c = (i >> 12) & 7, hw = i & 4095;
    int y = hw >> 6, xx = hw & 63;
    g_zqp[(size_t)(n * 8 + c) * Z_P + (y + 1) * 68 + xx + 1] = q;
    float diff = g_z[i] - q;
    float v = diff * diff;
    __shared__ float red[256];
    red[threadIdx.x] = v; __syncthreads();
    for (int s = 128; s > 0; s >>= 1) {
        if (threadIdx.x < s) red[threadIdx.x] += red[threadIdx.x + s];
        __syncthreads();
    }
    if (threadIdx.x == 0) g_part[blockIdx.x] = red[0];
}

__global__ __launch_bounds__(256) void k_loss(float* __restrict__ out) {
    __shared__ float red[256];
    float s = 0.f;
    for (int i = threadIdx.x; i < 4096; i += 256) s += g_part[i];
    red[threadIdx.x] = s; __syncthreads();
    for (int st = 128; st > 0; st >>= 1) {
        if (threadIdx.x < st) red[threadIdx.x] += red[threadIdx.x + st];
        __syncthreads();
    }
    if (threadIdx.x == 0) out[LOSS_OFF] = red[0] * (1.25f / 1048576.f);
}

__global__ __launch_bounds__(256) void k_idxout(float* __restrict__ out) {
    int p = blockIdx.x * 256 + threadIdx.x;
    if (p < B * 4096) out[IDX_OFF + p] = (float)g_idx[p];
}

// =====================================================================
// dconv1: 3x3 p1, 8->64, ReLU. 8co x 8px. grid 512 x 256
// pipelined over idx = ci*3+ky (24 iters)
// =====================================================================
__global__ __launch_bounds__(256) void k_dconv1(const float* __restrict__ w,
                                                const float* __restrict__ bias) {
    __shared__ float ws[8 * 9 * 64];
    for (int i = threadIdx.x; i < 4608; i += 256) {
        int t = i >> 6, co = i & 63;
        int ci = t / 9, k = t % 9;
        ws[i] = w[(co * 8 + ci) * 9 + k];
    }
    __syncthreads();
    int n = blockIdx.x >> 4, oyg = blockIdx.x & 15;
    int cog = threadIdx.x >> 5, oyl = (threadIdx.x >> 3) & 3, v0 = threadIdx.x & 7;
    int oy = oyg * 4 + oyl, ox0 = v0 * 8;
    u64 acc[4][8];
#pragma unroll
    for (int cp = 0; cp < 4; cp++) {
        u64 bv = pack2(bias[cog * 8 + 2 * cp], bias[cog * 8 + 2 * cp + 1]);
#pragma unroll
        for (int j = 0; j < 8; j++) acc[cp][j] = bv;
    }
    const float* base = g_zqp + (size_t)n * 8 * Z_P + oy * 68 + ox0;
    S10 cur = ld10(base);
#pragma unroll 1
    for (int idx = 0; idx < 24; idx++) {
        int nx = idx < 23 ? idx + 1 : 23;
        S10 nxt = ld10(base + (nx / 3) * Z_P + (nx % 3) * 68);
        float f[10]; unp10(cur, f);
        u64 fb[10];
#pragma unroll
        for (int i = 0; i < 10; i++) fb[i] = pack2(f[i], f[i]);
        int ci = idx / 3, ky = idx % 3;
#pragma unroll
        for (int kx = 0; kx < 3; kx++) {
            const u64* wr = (const u64*)&ws[(ci * 9 + ky * 3 + kx) * 64 + cog * 8];
            u64 w0 = wr[0], w1 = wr[1], w2 = wr[2], w3 = wr[3];
#pragma unroll
            for (int j = 0; j < 8; j++) {
                u64 vv = fb[j + kx];
                FFMA2(acc[0][j], vv, w0); FFMA2(acc[1][j], vv, w1);
                FFMA2(acc[2][j], vv, w2); FFMA2(acc[3][j], vv, w3);
            }
        }
        cur = nxt;
    }
    float* o = g_d1p + (size_t)n * 64 * Z_P + (oy + 1) * 68 + ox0 + 1;
#pragma unroll
    for (int cp = 0; cp < 4; cp++)
#pragma unroll
        for (int j = 0; j < 8; j++) {
            float2 fo = unpack2(acc[cp][j]);
            o[(cog * 8 + 2 * cp)     * Z_P + j] = fmaxf(fo.x, 0.f);
            o[(cog * 8 + 2 * cp + 1) * Z_P + j] = fmaxf(fo.y, 0.f);
        }
}

// =====================================================================
// dect1: 64->64, parity sub-conv. 8co x 8v. grid (512, 4) x 256
// pipelined over cl (16 iters per cc chunk)
// =====================================================================
template<int PY, int PX>
__device__ __forceinline__ void dect1_body(const float* __restrict__ w,
                                           const float* __restrict__ bias) {
    __shared__ float ws[16 * 4 * 64];
    int n = blockIdx.x >> 4, ug = blockIdx.x & 15;
    int cog = threadIdx.x >> 5, ul = (threadIdx.x >> 3) & 3, v0 = threadIdx.x & 7;
    int u = ug * 4 + ul;
    u64 acc[4][8];
#pragma unroll
    for (int cp = 0; cp < 4; cp++) {
        u64 bv = pack2(bias[cog * 8 + 2 * cp], bias[cog * 8 + 2 * cp + 1]);
#pragma unroll
        for (int j = 0; j < 8; j++) acc[cp][j] = bv;
    }
    const float* xin = g_d1p + (size_t)n * 64 * Z_P + (u + PY) * 68 + v0 * 8;
#pragma unroll 1
    for (int cc = 0; cc < 4; cc++) {
        __syncthreads();
        for (int i = threadIdx.x; i < 4096; i += 256) {
            int co = i & 63, t = i >> 6;
            int cl = t >> 2, tp = t & 3;
            ws[i] = w[(co * 64 + cc * 16 + cl) * 16
                      + (PY + 2 * (tp >> 1)) * 4 + PX + 2 * (tp & 1)];
        }
        __syncthreads();
        const float* base = xin + cc * 16 * Z_P;
        S10 ca = ld10(base), cb = ld10(base + 68);
#pragma unroll 1
        for (int cl = 0; cl < 16; cl++) {
            const float* pn = base + (cl < 15 ? cl + 1 : cl) * Z_P;
            S10 na = ld10(pn), nb = ld10(pn + 68);
            float f0[10], f1[10]; unp10(ca, f0); unp10(cb, f1);
            u64 P0[9], P1[9];
#pragma unroll
            for (int i = 0; i < 9; i++) {
                P0[i] = pack2(f0[i + PX], f0[i + PX]);
                P1[i] = pack2(f1[i + PX], f1[i + PX]);
            }
            const u64* wb = (const u64*)&ws[cl * 4 * 64 + cog * 8];
            u64 w00[4], w01[4], w10[4], w11[4];
#pragma unroll
            for (int cp = 0; cp < 4; cp++) {
                w00[cp] = wb[cp]; w01[cp] = wb[32 + cp];
                w10[cp] = wb[64 + cp]; w11[cp] = wb[96 + cp];
            }
#pragma unroll
            for (int j = 0; j < 8; j++) {
#pragma unroll
                for (int cp = 0; cp < 4; cp++) {
                    FFMA2(acc[cp][j], P0[j],     w00[cp]);
                    FFMA2(acc[cp][j], P0[j + 1], w01[cp]);
                    FFMA2(acc[cp][j], P1[j],     w10[cp]);
                    FFMA2(acc[cp][j], P1[j + 1], w11[cp]);
                }
            }
            ca = na; cb = nb;
        }
    }
    float* o = g_t1p + (size_t)n * 64 * H1_P + (2 * u + PY + 1) * 132
             + 2 * (v0 * 8) + PX + 1;
#pragma unroll
    for (int cp = 0; cp < 4; cp++)
#pragma unroll
        for (int j = 0; j < 8; j++) {
            float2 fo = unpack2(acc[cp][j]);
            o[(cog * 8 + 2 * cp)     * H1_P + 2 * j] = fmaxf(fo.x, 0.f);
            o[(cog * 8 + 2 * cp + 1) * H1_P + 2 * j] = fmaxf(fo.y, 0.f);
        }
}

__global__ __launch_bounds__(256) void k_dect1(const float* __restrict__ w,
                                               const float* __restrict__ bias) {
    switch (blockIdx.y) {
        case 0: dect1_body<0, 0>(w, bias); break;
        case 1: dect1_body<0, 1>(w, bias); break;
        case 2: dect1_body<1, 0>(w, bias); break;
        default: dect1_body<1, 1>(w, bias); break;
    }
}

// =====================================================================
// dect2: 64->32, parity sub-conv. 8co x 8v. grid (1024,4) x 256
// pipelined over cl (32 iters per cc chunk)
// =====================================================================
template<int PY, int PX>
__device__ __forceinline__ void dect2_body(const float* __restrict__ w,
                                           const float* __restrict__ bias) {
    __shared__ float ws[32 * 4 * 32];
    int n = blockIdx.x >> 5, ug = blockIdx.x & 31;
    int cog = threadIdx.x >> 6, ul = (threadIdx.x >> 4) & 3, v0 = threadIdx.x & 15;
    int u = ug * 4 + ul;
    u64 acc[4][8];
#pragma unroll
    for (int cp = 0; cp < 4; cp++) {
        u64 bv = pack2(bias[cog * 8 + 2 * cp], bias[cog * 8 + 2 * cp + 1]);
#pragma unroll
        for (int j = 0; j < 8; j++) acc[cp][j] = bv;
    }
    const float* xin = g_t1p + (size_t)n * 64 * H1_P + (u + PY) * 132 + v0 * 8;
#pragma unroll 1
    for (int cc = 0; cc < 2; cc++) {
        __syncthreads();
        for (int i = threadIdx.x; i < 4096; i += 256) {
            int co = i & 31, t = i >> 5;
            int cl = t >> 2, tp = t & 3;
            ws[i] = w[(co * 64 + cc * 32 + cl) * 16
                      + (PY + 2 * (tp >> 1)) * 4 + PX + 2 * (tp & 1)];
        }
        __syncthreads();
        const float* base = xin + cc * 32 * H1_P;
        S10 ca = ld10(base), cb = ld10(base + 132);
#pragma unroll 1
        for (int cl = 0; cl < 32; cl++) {
            const float* pn = base + (cl < 31 ? cl + 1 : cl) * H1_P;
            S10 na = ld10(pn), nb = ld10(pn + 132);
            float f0[10], f1[10]; unp10(ca, f0); unp10(cb, f1);
            u64 P0[9], P1[9];
#pragma unroll
            for (int i = 0; i < 9; i++) {
                P0[i] = pack2(f0[i + PX], f0[i + PX]);
                P1[i] = pack2(f1[i + PX], f1[i + PX]);
            }
            const u64* wb = (const u64*)&ws[cl * 4 * 32 + cog * 8];
            u64 w00[4], w01[4], w10[4], w11[4];
#pragma unroll
            for (int cp = 0; cp < 4; cp++) {
                w00[cp] = wb[cp]; w01[cp] = wb[16 + cp];
                w10[cp] = wb[32 + cp]; w11[cp] = wb[48 + cp];
            }
#pragma unroll
            for (int j = 0; j < 8; j++) {
#pragma unroll
                for (int cp = 0; cp < 4; cp++) {
                    FFMA2(acc[cp][j], P0[j],     w00[cp]);
                    FFMA2(acc[cp][j], P0[j + 1], w01[cp]);
                    FFMA2(acc[cp][j], P1[j],     w10[cp]);
                    FFMA2(acc[cp][j], P1[j + 1], w11[cp]);
                }
            }
            ca = na; cb = nb;
        }
    }
    float* o = g_t2p + (size_t)n * 32 * XP_P + (2 * u + PY + 1) * 260
             + 2 * (v0 * 8) + PX + 1;
#pragma unroll
    for (int cp = 0; cp < 4; cp++)
#pragma unroll
        for (int j = 0; j < 8; j++) {
            float2 fo = unpack2(acc[cp][j]);
            o[(cog * 8 + 2 * cp)     * XP_P + 2 * j] = fmaxf(fo.x, 0.f);
            o[(cog * 8 + 2 * cp + 1) * XP_P + 2 * j] = fmaxf(fo.y, 0.f);
        }
}

__global__ __launch_bounds__(256) void k_dect2(const float* __restrict__ w,
                                               const float* __restrict__ bias) {
    switch (blockIdx.y) {
        case 0: dect2_body<0, 0>(w, bias); break;
        case 1: dect2_body<0, 1>(w, bias); break;
        case 2: dect2_body<1, 0>(w, bias); break;
        default: dect2_body<1, 1>(w, bias); break;
    }
}

// =====================================================================
// dconv2: 3x3 p1, 32->3, sigmoid. 4 px/thread, pipelined over ci. grid 2048 x 256
// =====================================================================
__global__ __launch_bounds__(256) void k_dconv2(const float* __restrict__ w,
                                                const float* __restrict__ bias,
                                                float* __restrict__ out) {
    __shared__ u64 ws2[32 * 9 * 3];
    for (int i = threadIdx.x; i < 32 * 9; i += 256) {
        int ci = i / 9, k = i % 9;
#pragma unroll
        for (int co = 0; co < 3; co++) {
            float wv = w[(co * 32 + ci) * 9 + k];
            ws2[i * 3 + co] = pack2(wv, wv);
        }
    }
    __syncthreads();
    int n = blockIdx.x >> 6;
    int p = ((blockIdx.x & 63) << 8) + threadIdx.x;
    int X = p & 63, oy = p >> 6;
    int ox0 = 4 * X;

    u64 acc[3][2];
#pragma unroll
    for (int co = 0; co < 3; co++) {
        float bv = bias[co];
        acc[co][0] = pack2(bv, bv);
        acc[co][1] = acc[co][0];
    }
    const float* xin = g_t2p + (size_t)n * 32 * XP_P + oy * 260 + ox0;
    float4 cA[3]; float2 cB[3];
#pragma unroll
    for (int ry = 0; ry < 3; ry++) {
        cA[ry] = *(const float4*)(xin + ry * 260);
        cB[ry] = *(const float2*)(xin + ry * 260 + 4);
    }
#pragma unroll 1
    for (int ci = 0; ci < 32; ci++) {
        const float* pn = xin + (ci < 31 ? ci + 1 : ci) * XP_P;
        float4 nA[3]; float2 nB[3];
#pragma unroll
        for (int ry = 0; ry < 3; ry++) {
            nA[ry] = *(const float4*)(pn + ry * 260);
            nB[ry] = *(const float2*)(pn + ry * 260 + 4);
        }
        float in[3][6];
#pragma unroll
        for (int ry = 0; ry < 3; ry++) {
            *(float4*)&in[ry][0] = cA[ry];
            *(float2*)&in[ry][4] = cB[ry];
        }
        u64 pr[3][5];
#pragma unroll
        for (int ry = 0; ry < 3; ry++)
#pragma unroll
            for (int i = 0; i < 5; i++)
                pr[ry][i] = pack2(in[ry][i], in[ry][i + 1]);
#pragma unroll
        for (int ky = 0; ky < 3; ky++)
#pragma unroll
            for (int kx = 0; kx < 3; kx++) {
                const u64* wr = &ws2[(ci * 9 + ky * 3 + kx) * 3];
#pragma unroll
                for (int co = 0; co < 3; co++) {
                    FFMA2(acc[co][0], pr[ky][kx],     wr[co]);
                    FFMA2(acc[co][1], pr[ky][kx + 2], wr[co]);
                }
            }
#pragma unroll
        for (int ry = 0; ry < 3; ry++) { cA[ry] = nA[ry]; cB[ry] = nB[ry]; }
    }
    float* o = out + (size_t)n * 3 * 65536 + oy * 256 + ox0;
#pragma unroll
    for (int co = 0; co < 3; co++) {
        float2 f0 = unpack2(acc[co][0]);
        float2 f1 = unpack2(acc[co][1]);
        o[co * 65536 + 0] = 1.f / (1.f + expf(-f0.x));
        o[co * 65536 + 1] = 1.f / (1.f + expf(-f0.y));
        o[co * 65536 + 2] = 1.f / (1.f + expf(-f1.x));
        o[co * 65536 + 3] = 1.f / (1.f + expf(-f1.y));
    }
}

// =====================================================================
extern "C" void kernel_launch(void* const* d_in, const int* in_sizes, int n_in,
                              void* d_out, int out_size) {
    const float* x       = (const float*)d_in[0];
    const float* enc_w1  = (const float*)d_in[1];
    const float* enc_b1  = (const float*)d_in[2];
    const float* enc_w2  = (const float*)d_in[3];
    const float* enc_b2  = (const float*)d_in[4];
    const float* enc_w3  = (const float*)d_in[5];
    const float* enc_b3  = (const float*)d_in[6];
    const float* codebook= (const float*)d_in[7];
    const float* dec_w1  = (const float*)d_in[8];
    const float* dec_b1  = (const float*)d_in[9];
    const float* dect_w1 = (const float*)d_in[10];
    const float* dect_b1 = (const float*)d_in[11];
    const float* dect_w2 = (const float*)d_in[12];
    const float* dect_b2 = (const float*)d_in[13];
    const float* dec_w2  = (const float*)d_in[14];
    const float* dec_b2  = (const float*)d_in[15];
    float* out = (float*)d_out;

    k_pad   <<<24576, 256>>>(x);
    k_conv1 <<<1024,  256>>>(enc_w1, enc_b1);
    k_conv2 <<<512,   256>>>(enc_w2, enc_b2);
    k_conv3 <<<512,   256>>>(enc_w3, enc_b3);
    k_vq    <<<1024,  128>>>(codebook);
    k_zq    <<<4096,  256>>>(codebook);
    k_loss  <<<1,     256>>>(out);
    k_idxout<<<512,   256>>>(out);
    k_dconv1<<<512,   256>>>(dec_w1, dec_b1);
    k_dect1 <<<dim3(512, 4),  256>>>(dect_w1, dect_b1);
    k_dect2 <<<dim3(1024, 4), 256>>>(dect_w2, dect_b2);
    k_dconv2<<<2048,  256>>>(dec_w2, dec_b2, out);
}